// round 2
// baseline (speedup 1.0000x reference)
#include <cuda_runtime.h>
#include <cstdint>

#define NMAX 50000
#define F 512
#define H 128

// ---- scratch (static device globals: no allocation allowed) ----
__device__ float g_x[(size_t)NMAX * H];      // (h*out_norm) @ W
__device__ float g_agg[(size_t)NMAX * H];    // scatter accumulator
__device__ int   g_deg_out[NMAX];
__device__ int   g_deg_in[NMAX];
__device__ float g_out_norm[NMAX];
__device__ float g_in_norm[NMAX];

// packed f32x2 FMA: d = a*b + d (each operand is a pair of fp32 in a 64-bit reg)
#define FFMA2(d, a, b) \
    asm("fma.rn.f32x2 %0, %1, %2, %0;" : "+l"(d) : "l"(a), "l"(b))

// ---- zero accumulators (must happen every launch: graph replays) ----
__global__ void zero_kernel(int n) {
    int total4 = n * (H / 4);
    float4 z = make_float4(0.f, 0.f, 0.f, 0.f);
    for (int i = blockIdx.x * blockDim.x + threadIdx.x; i < total4;
         i += gridDim.x * blockDim.x) {
        reinterpret_cast<float4*>(g_agg)[i] = z;
        if (i < n) { g_deg_out[i] = 0; g_deg_in[i] = 0; }
    }
}

// ---- degree histograms ----
__global__ void deg_kernel(const int* __restrict__ src,
                           const int* __restrict__ dst, int e) {
    int i = blockIdx.x * blockDim.x + threadIdx.x;
    if (i < e) {
        atomicAdd(&g_deg_out[src[i]], 1);
        atomicAdd(&g_deg_in[dst[i]], 1);
    }
}

// ---- deg -> norm ----
__global__ void norm_kernel(int n) {
    int i = blockIdx.x * blockDim.x + threadIdx.x;
    if (i < n) {
        g_out_norm[i] = rsqrtf((float)max(g_deg_out[i], 1));
        g_in_norm[i]  = rsqrtf((float)max(g_deg_in[i], 1));
    }
}

// ---- GEMM: g_x = (h * out_norm[:,None]) @ W ; [n,512]@[512,128] ----
// Block tile 64x128, K-tile 32, 256 threads, per-thread 8 rows x 4 cols.
// Inner loop uses packed fma.rn.f32x2: accumulators are column pairs, the
// A operand is duplicated in shared memory so (a,a) pairs load directly,
// and B float4 loads provide (b0,b1),(b2,b3) pairs naturally.
__global__ __launch_bounds__(256) void gemm_kernel(const float* __restrict__ hin,
                                                   const float* __restrict__ W,
                                                   int n) {
    // As2[row][2k+0..1] both hold A[row][k] (duplicated), row padded to 68
    __shared__ float As2[64][68];
    __shared__ float Bs[32][128];

    const int tid  = threadIdx.x;
    const int tx   = tid & 31;   // output col group: cols tx*4..tx*4+3
    const int ty   = tid >> 5;   // warp id -> rows ty*8..ty*8+7 (broadcast A)
    const int brow = blockIdx.x * 64;

    // acc2[r][p]: packed pair of columns (tx*4+2p, tx*4+2p+1) for row ty*8+r
    uint64_t acc2[8][2];
#pragma unroll
    for (int r = 0; r < 8; r++) { acc2[r][0] = 0ull; acc2[r][1] = 0ull; }

    // A-load mapping: thread -> (row, 4 k's); two passes cover 64 rows
    const int a_row = tid >> 3;        // 0..31
    const int a_k4  = (tid & 7) * 4;   // 0,4,..,28
    // B-load mapping: thread -> (k row, 4 cols); four passes cover 32 k's
    const int b_k  = tid >> 5;         // 0..7
    const int b_c4 = (tid & 31) * 4;   // 0..124

    const int  r0ok = (brow + a_row) < n;
    const int  r1ok = (brow + a_row + 32) < n;
    const float s0 = r0ok ? g_out_norm[brow + a_row] : 0.f;
    const float s1 = r1ok ? g_out_norm[brow + a_row + 32] : 0.f;

    for (int k0 = 0; k0 < F; k0 += 32) {
        float4 a0 = make_float4(0.f, 0.f, 0.f, 0.f);
        float4 a1 = make_float4(0.f, 0.f, 0.f, 0.f);
        if (r0ok)
            a0 = *reinterpret_cast<const float4*>(
                &hin[(size_t)(brow + a_row) * F + k0 + a_k4]);
        if (r1ok)
            a1 = *reinterpret_cast<const float4*>(
                &hin[(size_t)(brow + a_row + 32) * F + k0 + a_k4]);
        a0.x *= s0; a0.y *= s0; a0.z *= s0; a0.w *= s0;
        a1.x *= s1; a1.y *= s1; a1.z *= s1; a1.w *= s1;
        // duplicated stores: cols 2*a_k4 .. 2*a_k4+7
        *reinterpret_cast<float4*>(&As2[a_row][2 * a_k4]) =
            make_float4(a0.x, a0.x, a0.y, a0.y);
        *reinterpret_cast<float4*>(&As2[a_row][2 * a_k4 + 4]) =
            make_float4(a0.z, a0.z, a0.w, a0.w);
        *reinterpret_cast<float4*>(&As2[a_row + 32][2 * a_k4]) =
            make_float4(a1.x, a1.x, a1.y, a1.y);
        *reinterpret_cast<float4*>(&As2[a_row + 32][2 * a_k4 + 4]) =
            make_float4(a1.z, a1.z, a1.w, a1.w);

#pragma unroll
        for (int i = 0; i < 4; i++) {
            int kk = b_k + i * 8;
            *reinterpret_cast<float4*>(&Bs[kk][b_c4]) =
                *reinterpret_cast<const float4*>(&W[(size_t)(k0 + kk) * H + b_c4]);
        }
        __syncthreads();

#pragma unroll
        for (int kk = 0; kk < 32; kk += 2) {
            // B pairs for kk and kk+1 at this thread's 4 columns
            ulonglong2 bA = *reinterpret_cast<ulonglong2*>(&Bs[kk][tx * 4]);
            ulonglong2 bB = *reinterpret_cast<ulonglong2*>(&Bs[kk + 1][tx * 4]);
#pragma unroll
            for (int r = 0; r < 8; r++) {
                // (a,a) duplicated pairs for kk (in .x) and kk+1 (in .y)
                ulonglong2 a2 = *reinterpret_cast<ulonglong2*>(
                    &As2[ty * 8 + r][2 * kk]);
                FFMA2(acc2[r][0], a2.x, bA.x);
                FFMA2(acc2[r][1], a2.x, bA.y);
                FFMA2(acc2[r][0], a2.y, bB.x);
                FFMA2(acc2[r][1], a2.y, bB.y);
            }
        }
        __syncthreads();
    }

#pragma unroll
    for (int r = 0; r < 8; r++) {
        int gr = brow + ty * 8 + r;
        if (gr < n) {
            float2 lo = *reinterpret_cast<float2*>(&acc2[r][0]);
            float2 hi = *reinterpret_cast<float2*>(&acc2[r][1]);
            float4 o = make_float4(lo.x, lo.y, hi.x, hi.y);
            *reinterpret_cast<float4*>(&g_x[(size_t)gr * H + tx * 4]) = o;
        }
    }
}

// ---- edge scatter: agg[dst] += x[src] ; one warp per edge, v4 reductions ----
__global__ __launch_bounds__(256) void scatter_kernel(const int* __restrict__ src,
                                                      const int* __restrict__ dst,
                                                      int e) {
    int edge = blockIdx.x * 8 + (threadIdx.x >> 5);
    if (edge >= e) return;
    int lane = threadIdx.x & 31;
    int s = src[edge];
    int d = dst[edge];
    float4 v = *reinterpret_cast<const float4*>(&g_x[(size_t)s * H + lane * 4]);
    float* p = &g_agg[(size_t)d * H + lane * 4];
    asm volatile("red.global.add.v4.f32 [%0], {%1, %2, %3, %4};"
                 :: "l"(p), "f"(v.x), "f"(v.y), "f"(v.z), "f"(v.w)
                 : "memory");
}

// ---- fused in_norm + bias + LayerNorm: warp per node ----
__global__ __launch_bounds__(256) void ln_kernel(const float* __restrict__ bias,
                                                 const float* __restrict__ gamma,
                                                 const float* __restrict__ beta,
                                                 float* __restrict__ y, int n) {
    int node = blockIdx.x * 8 + (threadIdx.x >> 5);
    if (node >= n) return;
    int lane = threadIdx.x & 31;

    float s = g_in_norm[node];
    float4 v  = *reinterpret_cast<const float4*>(&g_agg[(size_t)node * H + lane * 4]);
    float4 bb = *reinterpret_cast<const float4*>(&bias[lane * 4]);
    v.x = v.x * s + bb.x;
    v.y = v.y * s + bb.y;
    v.z = v.z * s + bb.z;
    v.w = v.w * s + bb.w;

    float sum = v.x + v.y + v.z + v.w;
#pragma unroll
    for (int o = 16; o; o >>= 1) sum += __shfl_xor_sync(0xffffffffu, sum, o);
    float mu = sum * (1.f / 128.f);

    float dx = v.x - mu, dy = v.y - mu, dz = v.z - mu, dw = v.w - mu;
    float sq = dx * dx + dy * dy + dz * dz + dw * dw;
#pragma unroll
    for (int o = 16; o; o >>= 1) sq += __shfl_xor_sync(0xffffffffu, sq, o);
    float rstd = rsqrtf(sq * (1.f / 128.f) + 1e-5f);

    float4 g  = *reinterpret_cast<const float4*>(&gamma[lane * 4]);
    float4 be = *reinterpret_cast<const float4*>(&beta[lane * 4]);
    float4 o4;
    o4.x = dx * rstd * g.x + be.x;
    o4.y = dy * rstd * g.y + be.y;
    o4.z = dz * rstd * g.z + be.z;
    o4.w = dw * rstd * g.w + be.w;
    *reinterpret_cast<float4*>(&y[(size_t)node * H + lane * 4]) = o4;
}

extern "C" void kernel_launch(void* const* d_in, const int* in_sizes, int n_in,
                              void* d_out, int out_size) {
    const float* h     = (const float*)d_in[0];
    const int*   src   = (const int*)d_in[1];
    const int*   dst   = (const int*)d_in[2];
    const float* W     = (const float*)d_in[3];
    const float* b     = (const float*)d_in[4];
    const float* gamma = (const float*)d_in[5];
    const float* beta  = (const float*)d_in[6];
    float* y = (float*)d_out;

    int n = in_sizes[0] / F;   // 50000
    int e = in_sizes[1];       // 800000

    zero_kernel<<<1024, 256>>>(n);
    deg_kernel<<<(e + 255) / 256, 256>>>(src, dst, e);
    norm_kernel<<<(n + 255) / 256, 256>>>(n);
    gemm_kernel<<<(n + 63) / 64, 256>>>(h, W, n);
    scatter_kernel<<<(e + 7) / 8, 256>>>(src, dst, e);
    ln_kernel<<<(n + 7) / 8, 256>>>(b, gamma, beta, y, n);
}

// round 4
// speedup vs baseline: 1.2494x; 1.2494x over previous
#include <cuda_runtime.h>
#include <cuda_bf16.h>
#include <cstdint>

#define NMAX 50000
#define F 512
#define H 128

// ---- scratch (static device globals: no allocation allowed) ----
__device__ float    g_x[(size_t)NMAX * H];     // (h*out_norm) @ W
__device__ float    g_agg[(size_t)NMAX * H];   // scatter accumulator
__device__ int      g_deg_out[NMAX];
__device__ int      g_deg_in[NMAX];
__device__ float    g_out_norm[NMAX];
__device__ float    g_in_norm[NMAX];
__device__ uint16_t g_Wh[(size_t)H * F];       // bf16 hi of W^T: [n][k]
__device__ uint16_t g_Wl[(size_t)H * F];       // bf16 lo of W^T: [n][k]

// ---- zero accumulators (must happen every launch: graph replays) ----
__global__ void zero_kernel(int n) {
    int total4 = n * (H / 4);
    float4 z = make_float4(0.f, 0.f, 0.f, 0.f);
    for (int i = blockIdx.x * blockDim.x + threadIdx.x; i < total4;
         i += gridDim.x * blockDim.x) {
        reinterpret_cast<float4*>(g_agg)[i] = z;
        if (i < n) { g_deg_out[i] = 0; g_deg_in[i] = 0; }
    }
}

// ---- degree histograms ----
__global__ void deg_kernel(const int* __restrict__ src,
                           const int* __restrict__ dst, int e) {
    int i = blockIdx.x * blockDim.x + threadIdx.x;
    if (i < e) {
        atomicAdd(&g_deg_out[src[i]], 1);
        atomicAdd(&g_deg_in[dst[i]], 1);
    }
}

// ---- deg -> norm ----
__global__ void norm_kernel(int n) {
    int i = blockIdx.x * blockDim.x + threadIdx.x;
    if (i < n) {
        g_out_norm[i] = rsqrtf((float)max(g_deg_out[i], 1));
        g_in_norm[i]  = rsqrtf((float)max(g_deg_in[i], 1));
    }
}

// ---- split W into transposed bf16 hi/lo (tiny: 65536 elems) ----
__global__ void wconv_kernel(const float* __restrict__ W) {
    int i = blockIdx.x * blockDim.x + threadIdx.x;
    if (i < H * F) {
        int nn = i >> 9;        // 0..127
        int k  = i & (F - 1);   // 0..511
        float w = W[(size_t)k * H + nn];
        __nv_bfloat16 hv = __float2bfloat16_rn(w);
        __nv_bfloat16 lv = __float2bfloat16_rn(w - __bfloat162float(hv));
        g_Wh[i] = *reinterpret_cast<uint16_t*>(&hv);
        g_Wl[i] = *reinterpret_cast<uint16_t*>(&lv);
    }
}

// ============================================================
// Tensor-core GEMM via mma.sync bf16x3:
//   g_x = (h * out_norm[:,None]) @ W,  [n,512] @ [512,128]
// CTA: 128 rows x 128 cols; 8 warps as 4(m) x 2(n); warp tile 32x64.
// K processed in 8 chunks of 64. smem tiles padded to 72 halves/row
// (row stride 144B -> conflict-free m16n8k16 fragment loads).
// ============================================================
#define KT 64
#define LDP 72   // padded row length in halves

#define SA_HI 0
#define SA_LO (128 * LDP)          // offsets in halves
#define SB_HI (2 * 128 * LDP)
#define SB_LO (3 * 128 * LDP)
#define SM_HALVES (4 * 128 * LDP)
#define SM_BYTES (SM_HALVES * 2)   // 73728

#define MMA_BF16(D, A, B0, B1)                                               \
    asm volatile(                                                            \
        "mma.sync.aligned.m16n8k16.row.col.f32.bf16.bf16.f32 "               \
        "{%0,%1,%2,%3}, {%4,%5,%6,%7}, {%8,%9}, {%0,%1,%2,%3};"              \
        : "+f"((D)[0]), "+f"((D)[1]), "+f"((D)[2]), "+f"((D)[3])             \
        : "r"((A)[0]), "r"((A)[1]), "r"((A)[2]), "r"((A)[3]),                \
          "r"(B0), "r"(B1))

__global__ __launch_bounds__(256) void gemm_mma_kernel(
    const float* __restrict__ hin, int n) {
    extern __shared__ uint16_t sm[];
    const int tid = threadIdx.x;
    const int wid = tid >> 5;
    const int lid = tid & 31;
    const int g = lid >> 2;          // groupID
    const int t = lid & 3;           // threadID_in_group
    const int wm = (wid & 3) * 32;   // warp row base within tile
    const int wn = (wid >> 2) * 64;  // warp col base within tile
    const int brow = blockIdx.x * 128;

    float d[2][8][4];
#pragma unroll
    for (int mf = 0; mf < 2; mf++)
#pragma unroll
        for (int nf = 0; nf < 8; nf++)
#pragma unroll
            for (int q = 0; q < 4; q++) d[mf][nf][q] = 0.f;

    // A-convert mapping: row = tid/2, 32-col half per thread
    const int arow  = tid >> 1;
    const int ahalf = (tid & 1) * 32;
    const int agrow = brow + arow;
    const bool a_ok = agrow < n;
    const float s   = a_ok ? g_out_norm[agrow] : 0.f;
    // B-copy mapping: n-row = tid/2, 32-k half per thread
    const int bn  = tid >> 1;
    const int bkh = (tid & 1) * 32;

    for (int c = 0; c < F / KT; c++) {
        const int k0 = c * KT;

        // ---- A chunk: scale, split to bf16 hi/lo, store padded smem ----
#pragma unroll
        for (int i = 0; i < 8; i++) {
            float4 v = make_float4(0.f, 0.f, 0.f, 0.f);
            if (a_ok)
                v = *reinterpret_cast<const float4*>(
                    &hin[(size_t)agrow * F + k0 + ahalf + i * 4]);
            v.x *= s; v.y *= s; v.z *= s; v.w *= s;
            __nv_bfloat162 h01 = __float22bfloat162_rn(make_float2(v.x, v.y));
            __nv_bfloat162 h23 = __float22bfloat162_rn(make_float2(v.z, v.w));
            float lx = v.x - __bfloat162float(__low2bfloat16(h01));
            float ly = v.y - __bfloat162float(__high2bfloat16(h01));
            float lz = v.z - __bfloat162float(__low2bfloat16(h23));
            float lw = v.w - __bfloat162float(__high2bfloat16(h23));
            __nv_bfloat162 l01 = __float22bfloat162_rn(make_float2(lx, ly));
            __nv_bfloat162 l23 = __float22bfloat162_rn(make_float2(lz, lw));
            uint2 hp, lp;
            hp.x = *reinterpret_cast<uint32_t*>(&h01);
            hp.y = *reinterpret_cast<uint32_t*>(&h23);
            lp.x = *reinterpret_cast<uint32_t*>(&l01);
            lp.y = *reinterpret_cast<uint32_t*>(&l23);
            int off = arow * LDP + ahalf + i * 4;
            *reinterpret_cast<uint2*>(&sm[SA_HI + off]) = hp;
            *reinterpret_cast<uint2*>(&sm[SA_LO + off]) = lp;
        }

        // ---- B chunk: copy pre-split bf16 W^T rows into padded smem ----
#pragma unroll
        for (int i = 0; i < 4; i++) {
            uint4 vh = *reinterpret_cast<const uint4*>(
                &g_Wh[(size_t)bn * F + k0 + bkh + i * 8]);
            uint4 vl = *reinterpret_cast<const uint4*>(
                &g_Wl[(size_t)bn * F + k0 + bkh + i * 8]);
            int off = bn * LDP + bkh + i * 8;
            *reinterpret_cast<uint2*>(&sm[SB_HI + off])     = make_uint2(vh.x, vh.y);
            *reinterpret_cast<uint2*>(&sm[SB_HI + off + 4]) = make_uint2(vh.z, vh.w);
            *reinterpret_cast<uint2*>(&sm[SB_LO + off])     = make_uint2(vl.x, vl.y);
            *reinterpret_cast<uint2*>(&sm[SB_LO + off + 4]) = make_uint2(vl.z, vl.w);
        }
        __syncthreads();

        // ---- MMA: 4 k-steps of 16; per step 2m x 8n x 3 terms ----
#pragma unroll
        for (int ks = 0; ks < 4; ks++) {
            const int kb = ks * 16;
            uint32_t ah[2][4], al[2][4];
#pragma unroll
            for (int mf = 0; mf < 2; mf++) {
                int r0 = (wm + mf * 16 + g) * LDP + kb + 2 * t;
                ah[mf][0] = *reinterpret_cast<uint32_t*>(&sm[SA_HI + r0]);
                ah[mf][1] = *reinterpret_cast<uint32_t*>(&sm[SA_HI + r0 + 8 * LDP]);
                ah[mf][2] = *reinterpret_cast<uint32_t*>(&sm[SA_HI + r0 + 8]);
                ah[mf][3] = *reinterpret_cast<uint32_t*>(&sm[SA_HI + r0 + 8 * LDP + 8]);
                al[mf][0] = *reinterpret_cast<uint32_t*>(&sm[SA_LO + r0]);
                al[mf][1] = *reinterpret_cast<uint32_t*>(&sm[SA_LO + r0 + 8 * LDP]);
                al[mf][2] = *reinterpret_cast<uint32_t*>(&sm[SA_LO + r0 + 8]);
                al[mf][3] = *reinterpret_cast<uint32_t*>(&sm[SA_LO + r0 + 8 * LDP + 8]);
            }
#pragma unroll
            for (int nf = 0; nf < 8; nf++) {
                int nb = (wn + nf * 8 + g) * LDP + kb + 2 * t;
                uint32_t bh0 = *reinterpret_cast<uint32_t*>(&sm[SB_HI + nb]);
                uint32_t bh1 = *reinterpret_cast<uint32_t*>(&sm[SB_HI + nb + 8]);
                uint32_t bl0 = *reinterpret_cast<uint32_t*>(&sm[SB_LO + nb]);
                uint32_t bl1 = *reinterpret_cast<uint32_t*>(&sm[SB_LO + nb + 8]);
#pragma unroll
                for (int mf = 0; mf < 2; mf++) {
                    MMA_BF16(d[mf][nf], ah[mf], bh0, bh1);  // Ah*Bh
                    MMA_BF16(d[mf][nf], ah[mf], bl0, bl1);  // Ah*Bl
                    MMA_BF16(d[mf][nf], al[mf], bh0, bh1);  // Al*Bh
                }
            }
        }
        __syncthreads();
    }

    // ---- epilogue: write fp32 result ----
#pragma unroll
    for (int mf = 0; mf < 2; mf++) {
        int row0 = brow + wm + mf * 16 + g;
        int row1 = row0 + 8;
#pragma unroll
        for (int nf = 0; nf < 8; nf++) {
            int col = wn + nf * 8 + 2 * t;
            if (row0 < n)
                *reinterpret_cast<float2*>(&g_x[(size_t)row0 * H + col]) =
                    make_float2(d[mf][nf][0], d[mf][nf][1]);
            if (row1 < n)
                *reinterpret_cast<float2*>(&g_x[(size_t)row1 * H + col]) =
                    make_float2(d[mf][nf][2], d[mf][nf][3]);
        }
    }
}

// ---- edge scatter: agg[dst] += x[src] ; one warp per edge, v4 reductions ----
__global__ __launch_bounds__(256) void scatter_kernel(const int* __restrict__ src,
                                                      const int* __restrict__ dst,
                                                      int e) {
    int edge = blockIdx.x * 8 + (threadIdx.x >> 5);
    if (edge >= e) return;
    int lane = threadIdx.x & 31;
    int s = src[edge];
    int d = dst[edge];
    float4 v = *reinterpret_cast<const float4*>(&g_x[(size_t)s * H + lane * 4]);
    float* p = &g_agg[(size_t)d * H + lane * 4];
    asm volatile("red.global.add.v4.f32 [%0], {%1, %2, %3, %4};"
                 :: "l"(p), "f"(v.x), "f"(v.y), "f"(v.z), "f"(v.w)
                 : "memory");
}

// ---- fused in_norm + bias + LayerNorm: warp per node ----
__global__ __launch_bounds__(256) void ln_kernel(const float* __restrict__ bias,
                                                 const float* __restrict__ gamma,
                                                 const float* __restrict__ beta,
                                                 float* __restrict__ y, int n) {
    int node = blockIdx.x * 8 + (threadIdx.x >> 5);
    if (node >= n) return;
    int lane = threadIdx.x & 31;

    float s = g_in_norm[node];
    float4 v  = *reinterpret_cast<const float4*>(&g_agg[(size_t)node * H + lane * 4]);
    float4 bb = *reinterpret_cast<const float4*>(&bias[lane * 4]);
    v.x = v.x * s + bb.x;
    v.y = v.y * s + bb.y;
    v.z = v.z * s + bb.z;
    v.w = v.w * s + bb.w;

    float sum = v.x + v.y + v.z + v.w;
#pragma unroll
    for (int o = 16; o; o >>= 1) sum += __shfl_xor_sync(0xffffffffu, sum, o);
    float mu = sum * (1.f / 128.f);

    float dx = v.x - mu, dy = v.y - mu, dz = v.z - mu, dw = v.w - mu;
    float sq = dx * dx + dy * dy + dz * dz + dw * dw;
#pragma unroll
    for (int o = 16; o; o >>= 1) sq += __shfl_xor_sync(0xffffffffu, sq, o);
    float rstd = rsqrtf(sq * (1.f / 128.f) + 1e-5f);

    float4 g  = *reinterpret_cast<const float4*>(&gamma[lane * 4]);
    float4 be = *reinterpret_cast<const float4*>(&beta[lane * 4]);
    float4 o4;
    o4.x = dx * rstd * g.x + be.x;
    o4.y = dy * rstd * g.y + be.y;
    o4.z = dz * rstd * g.z + be.z;
    o4.w = dw * rstd * g.w + be.w;
    *reinterpret_cast<float4*>(&y[(size_t)node * H + lane * 4]) = o4;
}

extern "C" void kernel_launch(void* const* d_in, const int* in_sizes, int n_in,
                              void* d_out, int out_size) {
    const float* h     = (const float*)d_in[0];
    const int*   src   = (const int*)d_in[1];
    const int*   dst   = (const int*)d_in[2];
    const float* W     = (const float*)d_in[3];
    const float* b     = (const float*)d_in[4];
    const float* gamma = (const float*)d_in[5];
    const float* beta  = (const float*)d_in[6];
    float* y = (float*)d_out;

    int n = in_sizes[0] / F;   // 50000
    int e = in_sizes[1];       // 800000

    static bool attr_set = false;
    if (!attr_set) {
        cudaFuncSetAttribute(gemm_mma_kernel,
                             cudaFuncAttributeMaxDynamicSharedMemorySize,
                             SM_BYTES);
        attr_set = true;
    }

    zero_kernel<<<1024, 256>>>(n);
    deg_kernel<<<(e + 255) / 256, 256>>>(src, dst, e);
    norm_kernel<<<(n + 255) / 256, 256>>>(n);
    wconv_kernel<<<(H * F + 255) / 256, 256>>>(W);
    gemm_mma_kernel<<<(n + 127) / 128, 256, SM_BYTES>>>(h, n);
    scatter_kernel<<<(e + 7) / 8, 256>>>(src, dst, e);
    ln_kernel<<<(n + 7) / 8, 256>>>(b, gamma, beta, y, n);
}

// round 5
// speedup vs baseline: 1.5636x; 1.2515x over previous
#include <cuda_runtime.h>
#include <cuda_fp16.h>
#include <cstdint>

#define NMAX 50000
#define F 512
#define H 128

// ---- scratch (static device globals: no allocation allowed) ----
__device__ float    g_x[(size_t)NMAX * H];     // (h*out_norm) @ W
__device__ float    g_agg[(size_t)NMAX * H];   // scatter accumulator
__device__ int      g_deg_out[NMAX];
__device__ int      g_deg_in[NMAX];
__device__ float    g_out_norm[NMAX];
__device__ float    g_in_norm[NMAX];
__device__ uint16_t g_Wh[(size_t)H * F];       // fp16 hi of W^T: [n][k]
__device__ uint16_t g_Wl[(size_t)H * F];       // fp16 lo of W^T: [n][k]

// ---- zero accumulators + W fp16 hi/lo split (fused; graph replays) ----
__global__ void zero_kernel(const float* __restrict__ W, int n) {
    int total4 = n * (H / 4);
    float4 z = make_float4(0.f, 0.f, 0.f, 0.f);
    for (int i = blockIdx.x * blockDim.x + threadIdx.x; i < total4;
         i += gridDim.x * blockDim.x) {
        reinterpret_cast<float4*>(g_agg)[i] = z;
        if (i < n) { g_deg_out[i] = 0; g_deg_in[i] = 0; }
        if (i < H * F) {
            int nn = i >> 9;        // 0..127
            int k  = i & (F - 1);   // 0..511
            float w = W[(size_t)k * H + nn];
            __half hv = __float2half_rn(w);
            __half lv = __float2half_rn(w - __half2float(hv));
            g_Wh[i] = *reinterpret_cast<uint16_t*>(&hv);
            g_Wl[i] = *reinterpret_cast<uint16_t*>(&lv);
        }
    }
}

// ---- degree histograms ----
__global__ void deg_kernel(const int* __restrict__ src,
                           const int* __restrict__ dst, int e) {
    int i = blockIdx.x * blockDim.x + threadIdx.x;
    if (i < e) {
        atomicAdd(&g_deg_out[src[i]], 1);
        atomicAdd(&g_deg_in[dst[i]], 1);
    }
}

// ---- deg -> norm ----
__global__ void norm_kernel(int n) {
    int i = blockIdx.x * blockDim.x + threadIdx.x;
    if (i < n) {
        g_out_norm[i] = rsqrtf((float)max(g_deg_out[i], 1));
        g_in_norm[i]  = rsqrtf((float)max(g_deg_in[i], 1));
    }
}

// ============================================================
// Tensor-core GEMM, fp16 2-term split (B = Bh + Bl; A single fp16):
//   g_x = (h * out_norm[:,None]) @ W,  error ~2^-12 (gate is 1e-3)
// CTA: 128 rows x 128 cols; 8 warps as 4(m) x 2(n); warp tile 32x64.
// K in 8 chunks of 64; smem rows padded to 72 halves (conflict-free
// ldmatrix: 144B row stride covers all 32 banks per 8-row phase).
// ============================================================
#define KT 64
#define LDP 72   // padded row length in halves

#define SA    0
#define SB_HI (128 * LDP)
#define SB_LO (2 * 128 * LDP)
#define SM_HALVES (3 * 128 * LDP)
#define SM_BYTES (SM_HALVES * 2)   // 55296

#define MMA_F16(D, A, B0, B1)                                                \
    asm volatile(                                                            \
        "mma.sync.aligned.m16n8k16.row.col.f32.f16.f16.f32 "                 \
        "{%0,%1,%2,%3}, {%4,%5,%6,%7}, {%8,%9}, {%0,%1,%2,%3};"              \
        : "+f"((D)[0]), "+f"((D)[1]), "+f"((D)[2]), "+f"((D)[3])             \
        : "r"((A)[0]), "r"((A)[1]), "r"((A)[2]), "r"((A)[3]),                \
          "r"(B0), "r"(B1))

#define LDMX4(R, PTR)                                                        \
    do {                                                                     \
        uint32_t _a = (uint32_t)__cvta_generic_to_shared(PTR);               \
        asm volatile(                                                        \
            "ldmatrix.sync.aligned.m8n8.x4.shared.b16 {%0,%1,%2,%3}, [%4];"  \
            : "=r"((R)[0]), "=r"((R)[1]), "=r"((R)[2]), "=r"((R)[3])         \
            : "r"(_a));                                                      \
    } while (0)

__global__ __launch_bounds__(256, 2) void gemm_mma_kernel(
    const float* __restrict__ hin, int n) {
    extern __shared__ uint16_t sm[];
    const int tid = threadIdx.x;
    const int wid = tid >> 5;
    const int lid = tid & 31;
    const int g = lid >> 2;          // groupID
    const int t = lid & 3;           // threadID_in_group
    const int wm = (wid & 3) * 32;   // warp row base within tile
    const int wn = (wid >> 2) * 64;  // warp col base within tile
    const int brow = blockIdx.x * 128;
    // ldmatrix lane -> (row offset, col offset) within a 16x16 tile
    const int ro = ((lid >> 3) & 1) * 8 + (lid & 7);
    const int co = (lid >> 4) * 8;

    float d[2][8][4];
#pragma unroll
    for (int mf = 0; mf < 2; mf++)
#pragma unroll
        for (int nf = 0; nf < 8; nf++)
#pragma unroll
            for (int q = 0; q < 4; q++) d[mf][nf][q] = 0.f;

    // A-convert mapping: row = tid/2, 32-col half per thread
    const int arow  = tid >> 1;
    const int ahalf = (tid & 1) * 32;
    const int agrow = brow + arow;
    const bool a_ok = agrow < n;
    const float s   = a_ok ? g_out_norm[agrow] : 0.f;
    // B-copy mapping: n-row = tid/2, 32-k half per thread
    const int bn  = tid >> 1;
    const int bkh = (tid & 1) * 32;

    for (int c = 0; c < F / KT; c++) {
        const int k0 = c * KT;

        // ---- A chunk: scale, convert fp32 -> fp16, store padded smem ----
#pragma unroll
        for (int i = 0; i < 8; i++) {
            float4 v = make_float4(0.f, 0.f, 0.f, 0.f);
            if (a_ok)
                v = *reinterpret_cast<const float4*>(
                    &hin[(size_t)agrow * F + k0 + ahalf + i * 4]);
            __half2 p01 = __float22half2_rn(make_float2(v.x * s, v.y * s));
            __half2 p23 = __float22half2_rn(make_float2(v.z * s, v.w * s));
            uint2 hp;
            hp.x = *reinterpret_cast<uint32_t*>(&p01);
            hp.y = *reinterpret_cast<uint32_t*>(&p23);
            *reinterpret_cast<uint2*>(&sm[SA + arow * LDP + ahalf + i * 4]) = hp;
        }

        // ---- B chunk: copy pre-split fp16 W^T rows into padded smem ----
#pragma unroll
        for (int i = 0; i < 4; i++) {
            uint4 vh = *reinterpret_cast<const uint4*>(
                &g_Wh[(size_t)bn * F + k0 + bkh + i * 8]);
            uint4 vl = *reinterpret_cast<const uint4*>(
                &g_Wl[(size_t)bn * F + k0 + bkh + i * 8]);
            int off = bn * LDP + bkh + i * 8;
            *reinterpret_cast<uint2*>(&sm[SB_HI + off])     = make_uint2(vh.x, vh.y);
            *reinterpret_cast<uint2*>(&sm[SB_HI + off + 4]) = make_uint2(vh.z, vh.w);
            *reinterpret_cast<uint2*>(&sm[SB_LO + off])     = make_uint2(vl.x, vl.y);
            *reinterpret_cast<uint2*>(&sm[SB_LO + off + 4]) = make_uint2(vl.z, vl.w);
        }
        __syncthreads();

        // ---- MMA: 4 k-steps of 16; ldmatrix fragments, 32 HMMA each ----
#pragma unroll
        for (int ks = 0; ks < 4; ks++) {
            const int kb = ks * 16;
            uint32_t a[2][4], bh[4][4], bl[4][4];
#pragma unroll
            for (int mf = 0; mf < 2; mf++)
                LDMX4(a[mf], &sm[SA + (wm + mf * 16 + ro) * LDP + kb + co]);
#pragma unroll
            for (int p = 0; p < 4; p++) {
                int rb = (wn + p * 16 + ro) * LDP + kb + co;
                LDMX4(bh[p], &sm[SB_HI + rb]);
                LDMX4(bl[p], &sm[SB_LO + rb]);
            }
#pragma unroll
            for (int nf = 0; nf < 8; nf++) {
                const int p = nf >> 1, sl = nf & 1;
                uint32_t b0h = bh[p][sl], b1h = bh[p][sl + 2];
                uint32_t b0l = bl[p][sl], b1l = bl[p][sl + 2];
#pragma unroll
                for (int mf = 0; mf < 2; mf++) {
                    MMA_F16(d[mf][nf], a[mf], b0h, b1h);  // A*Bh
                    MMA_F16(d[mf][nf], a[mf], b0l, b1l);  // A*Bl
                }
            }
        }
        __syncthreads();
    }

    // ---- epilogue: write fp32 result ----
#pragma unroll
    for (int mf = 0; mf < 2; mf++) {
        int row0 = brow + wm + mf * 16 + g;
        int row1 = row0 + 8;
#pragma unroll
        for (int nf = 0; nf < 8; nf++) {
            int col = wn + nf * 8 + 2 * t;
            if (row0 < n)
                *reinterpret_cast<float2*>(&g_x[(size_t)row0 * H + col]) =
                    make_float2(d[mf][nf][0], d[mf][nf][1]);
            if (row1 < n)
                *reinterpret_cast<float2*>(&g_x[(size_t)row1 * H + col]) =
                    make_float2(d[mf][nf][2], d[mf][nf][3]);
        }
    }
}

// ---- edge scatter: agg[dst] += x[src] ; one warp per edge, v4 reductions ----
__global__ __launch_bounds__(256) void scatter_kernel(const int* __restrict__ src,
                                                      const int* __restrict__ dst,
                                                      int e) {
    int edge = blockIdx.x * 8 + (threadIdx.x >> 5);
    if (edge >= e) return;
    int lane = threadIdx.x & 31;
    int s = src[edge];
    int d = dst[edge];
    float4 v = *reinterpret_cast<const float4*>(&g_x[(size_t)s * H + lane * 4]);
    float* p = &g_agg[(size_t)d * H + lane * 4];
    asm volatile("red.global.add.v4.f32 [%0], {%1, %2, %3, %4};"
                 :: "l"(p), "f"(v.x), "f"(v.y), "f"(v.z), "f"(v.w)
                 : "memory");
}

// ---- fused in_norm + bias + LayerNorm: warp per node ----
__global__ __launch_bounds__(256) void ln_kernel(const float* __restrict__ bias,
                                                 const float* __restrict__ gamma,
                                                 const float* __restrict__ beta,
                                                 float* __restrict__ y, int n) {
    int node = blockIdx.x * 8 + (threadIdx.x >> 5);
    if (node >= n) return;
    int lane = threadIdx.x & 31;

    float s = g_in_norm[node];
    float4 v  = *reinterpret_cast<const float4*>(&g_agg[(size_t)node * H + lane * 4]);
    float4 bb = *reinterpret_cast<const float4*>(&bias[lane * 4]);
    v.x = v.x * s + bb.x;
    v.y = v.y * s + bb.y;
    v.z = v.z * s + bb.z;
    v.w = v.w * s + bb.w;

    float sum = v.x + v.y + v.z + v.w;
#pragma unroll
    for (int o = 16; o; o >>= 1) sum += __shfl_xor_sync(0xffffffffu, sum, o);
    float mu = sum * (1.f / 128.f);

    float dx = v.x - mu, dy = v.y - mu, dz = v.z - mu, dw = v.w - mu;
    float sq = dx * dx + dy * dy + dz * dz + dw * dw;
#pragma unroll
    for (int o = 16; o; o >>= 1) sq += __shfl_xor_sync(0xffffffffu, sq, o);
    float rstd = rsqrtf(sq * (1.f / 128.f) + 1e-5f);

    float4 g  = *reinterpret_cast<const float4*>(&gamma[lane * 4]);
    float4 be = *reinterpret_cast<const float4*>(&beta[lane * 4]);
    float4 o4;
    o4.x = dx * rstd * g.x + be.x;
    o4.y = dy * rstd * g.y + be.y;
    o4.z = dz * rstd * g.z + be.z;
    o4.w = dw * rstd * g.w + be.w;
    *reinterpret_cast<float4*>(&y[(size_t)node * H + lane * 4]) = o4;
}

extern "C" void kernel_launch(void* const* d_in, const int* in_sizes, int n_in,
                              void* d_out, int out_size) {
    const float* h     = (const float*)d_in[0];
    const int*   src   = (const int*)d_in[1];
    const int*   dst   = (const int*)d_in[2];
    const float* W     = (const float*)d_in[3];
    const float* b     = (const float*)d_in[4];
    const float* gamma = (const float*)d_in[5];
    const float* beta  = (const float*)d_in[6];
    float* y = (float*)d_out;

    int n = in_sizes[0] / F;   // 50000
    int e = in_sizes[1];       // 800000

    static bool attr_set = false;
    if (!attr_set) {
        cudaFuncSetAttribute(gemm_mma_kernel,
                             cudaFuncAttributeMaxDynamicSharedMemorySize,
                             SM_BYTES);
        attr_set = true;
    }

    zero_kernel<<<1024, 256>>>(W, n);                      // 1
    deg_kernel<<<(e + 255) / 256, 256>>>(src, dst, e);     // 2
    norm_kernel<<<(n + 255) / 256, 256>>>(n);              // 3
    gemm_mma_kernel<<<(n + 127) / 128, 256, SM_BYTES>>>(h, n);  // 4 (profiled)
    scatter_kernel<<<(e + 7) / 8, 256>>>(src, dst, e);     // 5
    ln_kernel<<<(n + 7) / 8, 256>>>(b, gamma, beta, y, n); // 6
}

// round 6
// speedup vs baseline: 1.5850x; 1.0137x over previous
#include <cuda_runtime.h>
#include <cuda_fp16.h>
#include <cstdint>

#define NMAX 50000
#define EMAX 800000
#define F 512
#define H 128

// ---- scratch (static device globals: no allocation allowed) ----
__device__ float    g_x[(size_t)NMAX * H];     // (h*out_norm) @ W
__device__ int      g_deg_out[NMAX];
__device__ int      g_deg_in[NMAX];
__device__ float    g_out_norm[NMAX];
__device__ int      g_off[NMAX];               // CSR offsets (by dst)
__device__ int      g_cursor[NMAX];            // fill cursors
__device__ int      g_esrc[EMAX];              // src ids grouped by dst
__device__ uint16_t g_Wh[(size_t)H * F];       // fp16 hi of W^T: [n][k]
__device__ uint16_t g_Wl[(size_t)H * F];       // fp16 lo of W^T: [n][k]

// ---- zero degrees + W fp16 hi/lo split (graph replays every time) ----
__global__ void zero_kernel(const float* __restrict__ W, int n) {
    int i = blockIdx.x * blockDim.x + threadIdx.x;
    if (i < n) { g_deg_out[i] = 0; g_deg_in[i] = 0; }
    if (i < H * F) {
        int nn = i >> 9;        // 0..127
        int k  = i & (F - 1);   // 0..511
        float w = W[(size_t)k * H + nn];
        __half hv = __float2half_rn(w);
        __half lv = __float2half_rn(w - __half2float(hv));
        g_Wh[i] = *reinterpret_cast<uint16_t*>(&hv);
        g_Wl[i] = *reinterpret_cast<uint16_t*>(&lv);
    }
}

// ---- degree histograms ----
__global__ void deg_kernel(const int* __restrict__ src,
                           const int* __restrict__ dst, int e) {
    int i = blockIdx.x * blockDim.x + threadIdx.x;
    if (i < e) {
        atomicAdd(&g_deg_out[src[i]], 1);
        atomicAdd(&g_deg_in[dst[i]], 1);
    }
}

// ---- out-degree -> norm (in_norm computed inline in gather) ----
__global__ void norm_kernel(int n) {
    int i = blockIdx.x * blockDim.x + threadIdx.x;
    if (i < n) g_out_norm[i] = rsqrtf((float)max(g_deg_out[i], 1));
}

// ---- exclusive scan of g_deg_in -> g_off, g_cursor (single block) ----
__global__ __launch_bounds__(1024) void scan_kernel(int n) {
    __shared__ int tsum[1024];
    const int t = threadIdx.x;
    const int per = (n + 1023) / 1024;
    const int beg = t * per;
    const int end = min(beg + per, n);
    int s = 0;
    for (int i = beg; i < end; i++) s += g_deg_in[i];
    tsum[t] = s;
    __syncthreads();
    // Hillis-Steele inclusive scan over 1024 partials
    for (int off = 1; off < 1024; off <<= 1) {
        int v = (t >= off) ? tsum[t - off] : 0;
        __syncthreads();
        tsum[t] += v;
        __syncthreads();
    }
    int run = tsum[t] - s;  // exclusive base for this thread's range
    for (int i = beg; i < end; i++) {
        g_off[i] = run;
        g_cursor[i] = run;
        run += g_deg_in[i];
    }
}

// ---- CSR fill: group edge sources by destination ----
__global__ void fill_kernel(const int* __restrict__ src,
                            const int* __restrict__ dst, int e) {
    int i = blockIdx.x * blockDim.x + threadIdx.x;
    if (i < e) {
        int p = atomicAdd(&g_cursor[dst[i]], 1);
        g_esrc[p] = src[i];
    }
}

// ============================================================
// Tensor-core GEMM v3, fp16 2-term (B = Bh + Bl; A single fp16):
//   g_x = (h * out_norm[:,None]) @ W
// 512 threads: 16 warps as 4(m) x 4(n); warp tile 32x32.
// Double-buffered smem + cp.async B + register-staged A => one
// __syncthreads per K-chunk, loads overlap MMA.
// ============================================================
#define KT 64
#define LDP 72   // padded row length in halves (conflict-free ldmatrix)

#define SA(st)  ((st) * 128 * LDP)
#define SBH(st) ((2 + (st)) * 128 * LDP)
#define SBL(st) ((4 + (st)) * 128 * LDP)
#define SM_HALVES (6 * 128 * LDP)
#define SM_BYTES (SM_HALVES * 2)   // 110592

#define MMA_F16(D, A, B0, B1)                                                \
    asm volatile(                                                            \
        "mma.sync.aligned.m16n8k16.row.col.f32.f16.f16.f32 "                 \
        "{%0,%1,%2,%3}, {%4,%5,%6,%7}, {%8,%9}, {%0,%1,%2,%3};"              \
        : "+f"((D)[0]), "+f"((D)[1]), "+f"((D)[2]), "+f"((D)[3])             \
        : "r"((A)[0]), "r"((A)[1]), "r"((A)[2]), "r"((A)[3]),                \
          "r"(B0), "r"(B1))

#define LDMX4(R, PTR)                                                        \
    do {                                                                     \
        uint32_t _a = (uint32_t)__cvta_generic_to_shared(PTR);               \
        asm volatile(                                                        \
            "ldmatrix.sync.aligned.m8n8.x4.shared.b16 {%0,%1,%2,%3}, [%4];"  \
            : "=r"((R)[0]), "=r"((R)[1]), "=r"((R)[2]), "=r"((R)[3])         \
            : "r"(_a));                                                      \
    } while (0)

#define CPA16(DST_PTR, SRC_PTR)                                              \
    do {                                                                     \
        uint32_t _d = (uint32_t)__cvta_generic_to_shared(DST_PTR);           \
        asm volatile("cp.async.cg.shared.global [%0], [%1], 16;"             \
                     :: "r"(_d), "l"(SRC_PTR));                              \
    } while (0)

__global__ __launch_bounds__(512, 1) void gemm_mma_kernel(
    const float* __restrict__ hin, int n) {
    extern __shared__ uint16_t sm[];
    const int tid = threadIdx.x;
    const int wid = tid >> 5;
    const int lid = tid & 31;
    const int g = lid >> 2;          // groupID
    const int t = lid & 3;           // threadID_in_group
    const int wm = (wid & 3) * 32;   // warp row base
    const int wn = (wid >> 2) * 32;  // warp col base
    const int brow = blockIdx.x * 128;
    // ldmatrix lane -> (row offset, col offset) within a 16x16 tile
    const int ro = ((lid >> 3) & 1) * 8 + (lid & 7);
    const int co = (lid >> 4) * 8;

    float d[2][4][4];
#pragma unroll
    for (int mf = 0; mf < 2; mf++)
#pragma unroll
        for (int nf = 0; nf < 4; nf++)
#pragma unroll
            for (int q = 0; q < 4; q++) d[mf][nf][q] = 0.f;

    // A mapping: row = tid/4, 16 fp32 per thread per 64-chunk
    const int arow  = tid >> 2;
    const int acol  = (tid & 3) * 16;
    const int agrow = brow + arow;
    const bool a_ok = agrow < n;
    const float s   = a_ok ? g_out_norm[agrow] : 0.f;
    // B mapping: n-row = tid/4, two 8-half segments per thread
    const int bn   = tid >> 2;
    const int bseg = (tid & 3) * 16;

    float4 areg[4];
    // prologue: stage A chunk 0 into registers, cp.async B chunk 0 -> stage 0
#pragma unroll
    for (int i = 0; i < 4; i++)
        areg[i] = a_ok ? *reinterpret_cast<const float4*>(
                             &hin[(size_t)agrow * F + acol + i * 4])
                       : make_float4(0.f, 0.f, 0.f, 0.f);
    CPA16(&sm[SBH(0) + bn * LDP + bseg],     &g_Wh[(size_t)bn * F + bseg]);
    CPA16(&sm[SBH(0) + bn * LDP + bseg + 8], &g_Wh[(size_t)bn * F + bseg + 8]);
    CPA16(&sm[SBL(0) + bn * LDP + bseg],     &g_Wl[(size_t)bn * F + bseg]);
    CPA16(&sm[SBL(0) + bn * LDP + bseg + 8], &g_Wl[(size_t)bn * F + bseg + 8]);
    asm volatile("cp.async.commit_group;");

    for (int c = 0; c < F / KT; c++) {
        const int st = c & 1;

        // convert staged A registers -> fp16 smem (stage st)
#pragma unroll
        for (int i = 0; i < 4; i++) {
            __half2 p01 = __float22half2_rn(
                make_float2(areg[i].x * s, areg[i].y * s));
            __half2 p23 = __float22half2_rn(
                make_float2(areg[i].z * s, areg[i].w * s));
            uint2 hp;
            hp.x = *reinterpret_cast<uint32_t*>(&p01);
            hp.y = *reinterpret_cast<uint32_t*>(&p23);
            *reinterpret_cast<uint2*>(
                &sm[SA(st) + arow * LDP + acol + i * 4]) = hp;
        }
        // stage A chunk c+1 into registers (overlaps everything below)
        if (c < 7) {
            const int k1 = (c + 1) * KT;
#pragma unroll
            for (int i = 0; i < 4; i++)
                areg[i] = a_ok ? *reinterpret_cast<const float4*>(
                                     &hin[(size_t)agrow * F + k1 + acol + i * 4])
                               : make_float4(0.f, 0.f, 0.f, 0.f);
        }
        asm volatile("cp.async.wait_group 0;");  // B chunk c landed
        __syncthreads();  // A stores + B visible; all prior MMA reads done
        // cp.async B chunk c+1 into the other stage (overlaps MMA below)
        if (c < 7) {
            const int k1 = (c + 1) * KT;
            CPA16(&sm[SBH(st ^ 1) + bn * LDP + bseg],
                  &g_Wh[(size_t)bn * F + k1 + bseg]);
            CPA16(&sm[SBH(st ^ 1) + bn * LDP + bseg + 8],
                  &g_Wh[(size_t)bn * F + k1 + bseg + 8]);
            CPA16(&sm[SBL(st ^ 1) + bn * LDP + bseg],
                  &g_Wl[(size_t)bn * F + k1 + bseg]);
            CPA16(&sm[SBL(st ^ 1) + bn * LDP + bseg + 8],
                  &g_Wl[(size_t)bn * F + k1 + bseg + 8]);
            asm volatile("cp.async.commit_group;");
        }

        // ---- MMA: 4 k-steps of 16 ----
#pragma unroll
        for (int ks = 0; ks < 4; ks++) {
            const int kb = ks * 16;
            uint32_t a[2][4];
#pragma unroll
            for (int mf = 0; mf < 2; mf++)
                LDMX4(a[mf], &sm[SA(st) + (wm + mf * 16 + ro) * LDP + kb + co]);
#pragma unroll
            for (int nt = 0; nt < 2; nt++) {
                uint32_t bh[4], bl[4];
                int rb = (wn + nt * 16 + ro) * LDP + kb + co;
                LDMX4(bh, &sm[SBH(st) + rb]);
                LDMX4(bl, &sm[SBL(st) + rb]);
#pragma unroll
                for (int sl = 0; sl < 2; sl++) {
#pragma unroll
                    for (int mf = 0; mf < 2; mf++) {
                        MMA_F16(d[mf][nt * 2 + sl], a[mf], bh[sl], bh[sl + 2]);
                        MMA_F16(d[mf][nt * 2 + sl], a[mf], bl[sl], bl[sl + 2]);
                    }
                }
            }
        }
        // no trailing sync: next iteration writes the other stage
    }

    // ---- epilogue: write fp32 result ----
#pragma unroll
    for (int mf = 0; mf < 2; mf++) {
        int row0 = brow + wm + mf * 16 + g;
        int row1 = row0 + 8;
#pragma unroll
        for (int nf = 0; nf < 4; nf++) {
            int col = wn + nf * 8 + 2 * t;
            if (row0 < n)
                *reinterpret_cast<float2*>(&g_x[(size_t)row0 * H + col]) =
                    make_float2(d[mf][nf][0], d[mf][nf][1]);
            if (row1 < n)
                *reinterpret_cast<float2*>(&g_x[(size_t)row1 * H + col]) =
                    make_float2(d[mf][nf][2], d[mf][nf][3]);
        }
    }
}

// ---- fused CSR gather + in_norm + bias + LayerNorm: warp per node ----
__global__ __launch_bounds__(256) void gather_ln_kernel(
    const float* __restrict__ bias, const float* __restrict__ gamma,
    const float* __restrict__ beta, float* __restrict__ y, int n) {
    int node = blockIdx.x * 8 + (threadIdx.x >> 5);
    if (node >= n) return;
    int lane = threadIdx.x & 31;

    const int beg = g_off[node];
    const int cnt = g_deg_in[node];

    float4 acc = make_float4(0.f, 0.f, 0.f, 0.f);
    for (int base = 0; base < cnt; base += 32) {
        int m = min(32, cnt - base);
        int id = (lane < m) ? g_esrc[beg + base + lane] : 0;
#pragma unroll 4
        for (int j = 0; j < m; j++) {
            int sidx = __shfl_sync(0xffffffffu, id, j);
            float4 v = *reinterpret_cast<const float4*>(
                &g_x[(size_t)sidx * H + lane * 4]);
            acc.x += v.x; acc.y += v.y; acc.z += v.z; acc.w += v.w;
        }
    }

    const float si = rsqrtf((float)max(cnt, 1));
    float4 bb = *reinterpret_cast<const float4*>(&bias[lane * 4]);
    float4 v;
    v.x = acc.x * si + bb.x;
    v.y = acc.y * si + bb.y;
    v.z = acc.z * si + bb.z;
    v.w = acc.w * si + bb.w;

    float sum = v.x + v.y + v.z + v.w;
#pragma unroll
    for (int o = 16; o; o >>= 1) sum += __shfl_xor_sync(0xffffffffu, sum, o);
    float mu = sum * (1.f / 128.f);

    float dx = v.x - mu, dy = v.y - mu, dz = v.z - mu, dw = v.w - mu;
    float sq = dx * dx + dy * dy + dz * dz + dw * dw;
#pragma unroll
    for (int o = 16; o; o >>= 1) sq += __shfl_xor_sync(0xffffffffu, sq, o);
    float rstd = rsqrtf(sq * (1.f / 128.f) + 1e-5f);

    float4 gm = *reinterpret_cast<const float4*>(&gamma[lane * 4]);
    float4 be = *reinterpret_cast<const float4*>(&beta[lane * 4]);
    float4 o4;
    o4.x = dx * rstd * gm.x + be.x;
    o4.y = dy * rstd * gm.y + be.y;
    o4.z = dz * rstd * gm.z + be.z;
    o4.w = dw * rstd * gm.w + be.w;
    *reinterpret_cast<float4*>(&y[(size_t)node * H + lane * 4]) = o4;
}

extern "C" void kernel_launch(void* const* d_in, const int* in_sizes, int n_in,
                              void* d_out, int out_size) {
    const float* h     = (const float*)d_in[0];
    const int*   src   = (const int*)d_in[1];
    const int*   dst   = (const int*)d_in[2];
    const float* W     = (const float*)d_in[3];
    const float* b     = (const float*)d_in[4];
    const float* gamma = (const float*)d_in[5];
    const float* beta  = (const float*)d_in[6];
    float* y = (float*)d_out;

    int n = in_sizes[0] / F;   // 50000
    int e = in_sizes[1];       // 800000

    static bool attr_set = false;
    if (!attr_set) {
        cudaFuncSetAttribute(gemm_mma_kernel,
                             cudaFuncAttributeMaxDynamicSharedMemorySize,
                             SM_BYTES);
        attr_set = true;
    }

    zero_kernel<<<(H * F + 255) / 256, 256>>>(W, n);            // 1
    deg_kernel<<<(e + 255) / 256, 256>>>(src, dst, e);          // 2
    norm_kernel<<<(n + 255) / 256, 256>>>(n);                   // 3
    gemm_mma_kernel<<<(n + 127) / 128, 512, SM_BYTES>>>(h, n);  // 4 (profiled)
    scan_kernel<<<1, 1024>>>(n);                                // 5
    fill_kernel<<<(e + 255) / 256, 256>>>(src, dst, e);         // 6
    gather_ln_kernel<<<(n + 7) / 8, 256>>>(b, gamma, beta, y, n); // 7
}

// round 7
// speedup vs baseline: 2.6135x; 1.6489x over previous
#include <cuda_runtime.h>
#include <cuda_fp16.h>
#include <cstdint>

#define NMAX 50000
#define EMAX 800000
#define F 512
#define H 128

// ---- scratch (static device globals: no allocation allowed) ----
__device__ __half   g_x[(size_t)NMAX * H];     // (h*out_norm) @ W, fp16
__device__ int      g_deg_out[NMAX];
__device__ int      g_deg_in[NMAX];
__device__ float    g_out_norm[NMAX];
__device__ int      g_off[NMAX];               // CSR offsets (by dst)
__device__ int      g_cursor[NMAX];            // fill cursors
__device__ int      g_esrc[EMAX];              // src ids grouped by dst
__device__ int      g_base_ctr;                // scan block-base counter
__device__ uint16_t g_Wh[(size_t)H * F];       // fp16 hi of W^T: [n][k]
__device__ uint16_t g_Wl[(size_t)H * F];       // fp16 lo of W^T: [n][k]

// ---- zero degrees + counter + W fp16 hi/lo split (graph replays) ----
__global__ void zero_kernel(const float* __restrict__ W, int n) {
    int i = blockIdx.x * blockDim.x + threadIdx.x;
    if (i == 0) g_base_ctr = 0;
    if (i < n) { g_deg_out[i] = 0; g_deg_in[i] = 0; }
    if (i < H * F) {
        int nn = i >> 9;        // 0..127
        int k  = i & (F - 1);   // 0..511
        float w = W[(size_t)k * H + nn];
        __half hv = __float2half_rn(w);
        __half lv = __float2half_rn(w - __half2float(hv));
        g_Wh[i] = *reinterpret_cast<uint16_t*>(&hv);
        g_Wl[i] = *reinterpret_cast<uint16_t*>(&lv);
    }
}

// ---- degree histograms (int4 vectorized; e % 4 == 0 or tail guarded) ----
__global__ void deg_kernel(const int* __restrict__ src,
                           const int* __restrict__ dst, int e) {
    int i4 = (blockIdx.x * blockDim.x + threadIdx.x) * 4;
    if (i4 + 3 < e) {
        int4 s = *reinterpret_cast<const int4*>(&src[i4]);
        int4 d = *reinterpret_cast<const int4*>(&dst[i4]);
        atomicAdd(&g_deg_out[s.x], 1); atomicAdd(&g_deg_out[s.y], 1);
        atomicAdd(&g_deg_out[s.z], 1); atomicAdd(&g_deg_out[s.w], 1);
        atomicAdd(&g_deg_in[d.x], 1);  atomicAdd(&g_deg_in[d.y], 1);
        atomicAdd(&g_deg_in[d.z], 1);  atomicAdd(&g_deg_in[d.w], 1);
    } else {
        for (int i = i4; i < e; i++) {
            atomicAdd(&g_deg_out[src[i]], 1);
            atomicAdd(&g_deg_in[dst[i]], 1);
        }
    }
}

// ---- out-degree -> norm (in_norm computed inline in gather) ----
__global__ void norm_kernel(int n) {
    int i = blockIdx.x * blockDim.x + threadIdx.x;
    if (i < n) g_out_norm[i] = rsqrtf((float)max(g_deg_out[i], 1));
}

// ---- parallel exclusive scan: block-local scan + atomic block base ----
// Segment placement depends on atomic order (run-varying), but each node
// still owns a private contiguous segment -> output differs only in fp32
// summation order (same class as the atomic cursor fill below).
__global__ __launch_bounds__(256) void scan_kernel(int n) {
    __shared__ int s[256];
    __shared__ int base;
    const int t = threadIdx.x;
    const int i = blockIdx.x * 256 + t;
    int d = (i < n) ? g_deg_in[i] : 0;
    s[t] = d;
    __syncthreads();
#pragma unroll
    for (int off = 1; off < 256; off <<= 1) {
        int v = (t >= off) ? s[t - off] : 0;
        __syncthreads();
        s[t] += v;
        __syncthreads();
    }
    if (t == 255) base = atomicAdd(&g_base_ctr, s[255]);
    __syncthreads();
    if (i < n) {
        int o = base + s[t] - d;  // exclusive within block + global base
        g_off[i] = o;
        g_cursor[i] = o;
    }
}

// ---- CSR fill: group edge sources by destination ----
__global__ void fill_kernel(const int* __restrict__ src,
                            const int* __restrict__ dst, int e) {
    int i = blockIdx.x * blockDim.x + threadIdx.x;
    if (i < e) {
        int p = atomicAdd(&g_cursor[dst[i]], 1);
        g_esrc[p] = src[i];
    }
}

// ============================================================
// Tensor-core GEMM v3, fp16 2-term (B = Bh + Bl; A single fp16):
//   g_x = (h * out_norm[:,None]) @ W   (output stored fp16)
// 512 threads: 16 warps as 4(m) x 4(n); warp tile 32x32.
// Double-buffered smem + cp.async B + register-staged A.
// ============================================================
#define KT 64
#define LDP 72   // padded row length in halves (conflict-free ldmatrix)

#define SA(st)  ((st) * 128 * LDP)
#define SBH(st) ((2 + (st)) * 128 * LDP)
#define SBL(st) ((4 + (st)) * 128 * LDP)
#define SM_HALVES (6 * 128 * LDP)
#define SM_BYTES (SM_HALVES * 2)   // 110592

#define MMA_F16(D, A, B0, B1)                                                \
    asm volatile(                                                            \
        "mma.sync.aligned.m16n8k16.row.col.f32.f16.f16.f32 "                 \
        "{%0,%1,%2,%3}, {%4,%5,%6,%7}, {%8,%9}, {%0,%1,%2,%3};"              \
        : "+f"((D)[0]), "+f"((D)[1]), "+f"((D)[2]), "+f"((D)[3])             \
        : "r"((A)[0]), "r"((A)[1]), "r"((A)[2]), "r"((A)[3]),                \
          "r"(B0), "r"(B1))

#define LDMX4(R, PTR)                                                        \
    do {                                                                     \
        uint32_t _a = (uint32_t)__cvta_generic_to_shared(PTR);               \
        asm volatile(                                                        \
            "ldmatrix.sync.aligned.m8n8.x4.shared.b16 {%0,%1,%2,%3}, [%4];"  \
            : "=r"((R)[0]), "=r"((R)[1]), "=r"((R)[2]), "=r"((R)[3])         \
            : "r"(_a));                                                      \
    } while (0)

#define CPA16(DST_PTR, SRC_PTR)                                              \
    do {                                                                     \
        uint32_t _d = (uint32_t)__cvta_generic_to_shared(DST_PTR);           \
        asm volatile("cp.async.cg.shared.global [%0], [%1], 16;"             \
                     :: "r"(_d), "l"(SRC_PTR));                              \
    } while (0)

__global__ __launch_bounds__(512, 1) void gemm_mma_kernel(
    const float* __restrict__ hin, int n) {
    extern __shared__ uint16_t sm[];
    const int tid = threadIdx.x;
    const int wid = tid >> 5;
    const int lid = tid & 31;
    const int g = lid >> 2;          // groupID
    const int t = lid & 3;           // threadID_in_group
    const int wm = (wid & 3) * 32;   // warp row base
    const int wn = (wid >> 2) * 32;  // warp col base
    const int brow = blockIdx.x * 128;
    // ldmatrix lane -> (row offset, col offset) within a 16x16 tile
    const int ro = ((lid >> 3) & 1) * 8 + (lid & 7);
    const int co = (lid >> 4) * 8;

    float d[2][4][4];
#pragma unroll
    for (int mf = 0; mf < 2; mf++)
#pragma unroll
        for (int nf = 0; nf < 4; nf++)
#pragma unroll
            for (int q = 0; q < 4; q++) d[mf][nf][q] = 0.f;

    // A mapping: row = tid/4, 16 fp32 per thread per 64-chunk
    const int arow  = tid >> 2;
    const int acol  = (tid & 3) * 16;
    const int agrow = brow + arow;
    const bool a_ok = agrow < n;
    const float s   = a_ok ? g_out_norm[agrow] : 0.f;
    // B mapping: n-row = tid/4, two 8-half segments per thread
    const int bn   = tid >> 2;
    const int bseg = (tid & 3) * 16;

    float4 areg[4];
    // prologue: stage A chunk 0 into registers, cp.async B chunk 0 -> stage 0
#pragma unroll
    for (int i = 0; i < 4; i++)
        areg[i] = a_ok ? *reinterpret_cast<const float4*>(
                             &hin[(size_t)agrow * F + acol + i * 4])
                       : make_float4(0.f, 0.f, 0.f, 0.f);
    CPA16(&sm[SBH(0) + bn * LDP + bseg],     &g_Wh[(size_t)bn * F + bseg]);
    CPA16(&sm[SBH(0) + bn * LDP + bseg + 8], &g_Wh[(size_t)bn * F + bseg + 8]);
    CPA16(&sm[SBL(0) + bn * LDP + bseg],     &g_Wl[(size_t)bn * F + bseg]);
    CPA16(&sm[SBL(0) + bn * LDP + bseg + 8], &g_Wl[(size_t)bn * F + bseg + 8]);
    asm volatile("cp.async.commit_group;");

    for (int c = 0; c < F / KT; c++) {
        const int st = c & 1;

        // convert staged A registers -> fp16 smem (stage st)
#pragma unroll
        for (int i = 0; i < 4; i++) {
            __half2 p01 = __float22half2_rn(
                make_float2(areg[i].x * s, areg[i].y * s));
            __half2 p23 = __float22half2_rn(
                make_float2(areg[i].z * s, areg[i].w * s));
            uint2 hp;
            hp.x = *reinterpret_cast<uint32_t*>(&p01);
            hp.y = *reinterpret_cast<uint32_t*>(&p23);
            *reinterpret_cast<uint2*>(
                &sm[SA(st) + arow * LDP + acol + i * 4]) = hp;
        }
        // stage A chunk c+1 into registers (overlaps everything below)
        if (c < 7) {
            const int k1 = (c + 1) * KT;
#pragma unroll
            for (int i = 0; i < 4; i++)
                areg[i] = a_ok ? *reinterpret_cast<const float4*>(
                                     &hin[(size_t)agrow * F + k1 + acol + i * 4])
                               : make_float4(0.f, 0.f, 0.f, 0.f);
        }
        asm volatile("cp.async.wait_group 0;");  // B chunk c landed
        __syncthreads();  // A stores + B visible; all prior MMA reads done
        // cp.async B chunk c+1 into the other stage (overlaps MMA below)
        if (c < 7) {
            const int k1 = (c + 1) * KT;
            CPA16(&sm[SBH(st ^ 1) + bn * LDP + bseg],
                  &g_Wh[(size_t)bn * F + k1 + bseg]);
            CPA16(&sm[SBH(st ^ 1) + bn * LDP + bseg + 8],
                  &g_Wh[(size_t)bn * F + k1 + bseg + 8]);
            CPA16(&sm[SBL(st ^ 1) + bn * LDP + bseg],
                  &g_Wl[(size_t)bn * F + k1 + bseg]);
            CPA16(&sm[SBL(st ^ 1) + bn * LDP + bseg + 8],
                  &g_Wl[(size_t)bn * F + k1 + bseg + 8]);
            asm volatile("cp.async.commit_group;");
        }

        // ---- MMA: 4 k-steps of 16 ----
#pragma unroll
        for (int ks = 0; ks < 4; ks++) {
            const int kb = ks * 16;
            uint32_t a[2][4];
#pragma unroll
            for (int mf = 0; mf < 2; mf++)
                LDMX4(a[mf], &sm[SA(st) + (wm + mf * 16 + ro) * LDP + kb + co]);
#pragma unroll
            for (int nt = 0; nt < 2; nt++) {
                uint32_t bh[4], bl[4];
                int rb = (wn + nt * 16 + ro) * LDP + kb + co;
                LDMX4(bh, &sm[SBH(st) + rb]);
                LDMX4(bl, &sm[SBL(st) + rb]);
#pragma unroll
                for (int sl = 0; sl < 2; sl++) {
#pragma unroll
                    for (int mf = 0; mf < 2; mf++) {
                        MMA_F16(d[mf][nt * 2 + sl], a[mf], bh[sl], bh[sl + 2]);
                        MMA_F16(d[mf][nt * 2 + sl], a[mf], bl[sl], bl[sl + 2]);
                    }
                }
            }
        }
        // no trailing sync: next iteration writes the other stage
    }

    // ---- epilogue: write fp16 result ----
#pragma unroll
    for (int mf = 0; mf < 2; mf++) {
        int row0 = brow + wm + mf * 16 + g;
        int row1 = row0 + 8;
#pragma unroll
        for (int nf = 0; nf < 4; nf++) {
            int col = wn + nf * 8 + 2 * t;
            __half2 lo = __float22half2_rn(make_float2(d[mf][nf][0], d[mf][nf][1]));
            __half2 hi = __float22half2_rn(make_float2(d[mf][nf][2], d[mf][nf][3]));
            if (row0 < n)
                *reinterpret_cast<__half2*>(&g_x[(size_t)row0 * H + col]) = lo;
            if (row1 < n)
                *reinterpret_cast<__half2*>(&g_x[(size_t)row1 * H + col]) = hi;
        }
    }
}

// ---- fused CSR gather + in_norm + bias + LayerNorm: warp per node ----
__global__ __launch_bounds__(256) void gather_ln_kernel(
    const float* __restrict__ bias, const float* __restrict__ gamma,
    const float* __restrict__ beta, float* __restrict__ y, int n) {
    int node = blockIdx.x * 8 + (threadIdx.x >> 5);
    if (node >= n) return;
    int lane = threadIdx.x & 31;

    const int beg = g_off[node];
    const int cnt = g_deg_in[node];

    float4 acc = make_float4(0.f, 0.f, 0.f, 0.f);
    for (int base = 0; base < cnt; base += 32) {
        int m = min(32, cnt - base);
        int id = (lane < m) ? g_esrc[beg + base + lane] : 0;
#pragma unroll 4
        for (int j = 0; j < m; j++) {
            int sidx = __shfl_sync(0xffffffffu, id, j);
            uint2 raw = *reinterpret_cast<const uint2*>(
                &g_x[(size_t)sidx * H + lane * 4]);
            float2 f01 = __half22float2(*reinterpret_cast<__half2*>(&raw.x));
            float2 f23 = __half22float2(*reinterpret_cast<__half2*>(&raw.y));
            acc.x += f01.x; acc.y += f01.y; acc.z += f23.x; acc.w += f23.y;
        }
    }

    const float si = rsqrtf((float)max(cnt, 1));
    float4 bb = *reinterpret_cast<const float4*>(&bias[lane * 4]);
    float4 v;
    v.x = acc.x * si + bb.x;
    v.y = acc.y * si + bb.y;
    v.z = acc.z * si + bb.z;
    v.w = acc.w * si + bb.w;

    float sum = v.x + v.y + v.z + v.w;
#pragma unroll
    for (int o = 16; o; o >>= 1) sum += __shfl_xor_sync(0xffffffffu, sum, o);
    float mu = sum * (1.f / 128.f);

    float dx = v.x - mu, dy = v.y - mu, dz = v.z - mu, dw = v.w - mu;
    float sq = dx * dx + dy * dy + dz * dz + dw * dw;
#pragma unroll
    for (int o = 16; o; o >>= 1) sq += __shfl_xor_sync(0xffffffffu, sq, o);
    float rstd = rsqrtf(sq * (1.f / 128.f) + 1e-5f);

    float4 gm = *reinterpret_cast<const float4*>(&gamma[lane * 4]);
    float4 be = *reinterpret_cast<const float4*>(&beta[lane * 4]);
    float4 o4;
    o4.x = dx * rstd * gm.x + be.x;
    o4.y = dy * rstd * gm.y + be.y;
    o4.z = dz * rstd * gm.z + be.z;
    o4.w = dw * rstd * gm.w + be.w;
    *reinterpret_cast<float4*>(&y[(size_t)node * H + lane * 4]) = o4;
}

extern "C" void kernel_launch(void* const* d_in, const int* in_sizes, int n_in,
                              void* d_out, int out_size) {
    const float* h     = (const float*)d_in[0];
    const int*   src   = (const int*)d_in[1];
    const int*   dst   = (const int*)d_in[2];
    const float* W     = (const float*)d_in[3];
    const float* b     = (const float*)d_in[4];
    const float* gamma = (const float*)d_in[5];
    const float* beta  = (const float*)d_in[6];
    float* y = (float*)d_out;

    int n = in_sizes[0] / F;   // 50000
    int e = in_sizes[1];       // 800000

    static bool attr_set = false;
    if (!attr_set) {
        cudaFuncSetAttribute(gemm_mma_kernel,
                             cudaFuncAttributeMaxDynamicSharedMemorySize,
                             SM_BYTES);
        attr_set = true;
    }

    zero_kernel<<<(H * F + 255) / 256, 256>>>(W, n);            // 1
    deg_kernel<<<(e / 4 + 255) / 256, 256>>>(src, dst, e);      // 2
    norm_kernel<<<(n + 255) / 256, 256>>>(n);                   // 3
    gemm_mma_kernel<<<(n + 127) / 128, 512, SM_BYTES>>>(h, n);  // 4 (profiled)
    scan_kernel<<<(n + 255) / 256, 256>>>(n);                   // 5
    fill_kernel<<<(e + 255) / 256, 256>>>(src, dst, e);         // 6
    gather_ln_kernel<<<(n + 7) / 8, 256>>>(b, gamma, beta, y, n); // 7
}

// round 8
// speedup vs baseline: 2.6598x; 1.0177x over previous
#include <cuda_runtime.h>
#include <cuda_fp16.h>
#include <cstdint>

#define NMAX 50000
#define EMAX 800000
#define F 512
#define H 128

// ---- scratch (static device globals: no allocation allowed) ----
__device__ __half   g_x[(size_t)NMAX * H];     // (h*out_norm) @ W, fp16
__device__ int      g_deg_out[NMAX];
__device__ int      g_deg_in[NMAX];
__device__ float    g_out_norm[NMAX];
__device__ int      g_off[NMAX];               // CSR offsets (by dst)
__device__ int      g_cursor[NMAX];            // fill cursors
__device__ int      g_esrc[EMAX];              // src ids grouped by dst
__device__ int      g_base_ctr;                // scan block-base counter
__device__ uint16_t g_Wh[(size_t)H * F];       // fp16 hi of W^T: [n][k]
__device__ uint16_t g_Wl[(size_t)H * F];       // fp16 lo of W^T: [n][k]

// ---- zero degrees + counter + W fp16 hi/lo split (graph replays) ----
__global__ void zero_kernel(const float* __restrict__ W, int n) {
    int i = blockIdx.x * blockDim.x + threadIdx.x;
    if (i == 0) g_base_ctr = 0;
    if (i < n) { g_deg_out[i] = 0; g_deg_in[i] = 0; }
    if (i < H * F) {
        int nn = i >> 9;        // 0..127
        int k  = i & (F - 1);   // 0..511
        float w = W[(size_t)k * H + nn];
        __half hv = __float2half_rn(w);
        __half lv = __float2half_rn(w - __half2float(hv));
        g_Wh[i] = *reinterpret_cast<uint16_t*>(&hv);
        g_Wl[i] = *reinterpret_cast<uint16_t*>(&lv);
    }
}

// ---- degree histograms (int4 vectorized) ----
__global__ void deg_kernel(const int* __restrict__ src,
                           const int* __restrict__ dst, int e) {
    int i4 = (blockIdx.x * blockDim.x + threadIdx.x) * 4;
    if (i4 + 3 < e) {
        int4 s = *reinterpret_cast<const int4*>(&src[i4]);
        int4 d = *reinterpret_cast<const int4*>(&dst[i4]);
        atomicAdd(&g_deg_out[s.x], 1); atomicAdd(&g_deg_out[s.y], 1);
        atomicAdd(&g_deg_out[s.z], 1); atomicAdd(&g_deg_out[s.w], 1);
        atomicAdd(&g_deg_in[d.x], 1);  atomicAdd(&g_deg_in[d.y], 1);
        atomicAdd(&g_deg_in[d.z], 1);  atomicAdd(&g_deg_in[d.w], 1);
    } else {
        for (int i = i4; i < e; i++) {
            atomicAdd(&g_deg_out[src[i]], 1);
            atomicAdd(&g_deg_in[dst[i]], 1);
        }
    }
}

// ---- out-degree -> norm (in_norm computed inline in gather) ----
__global__ void norm_kernel(int n) {
    int i = blockIdx.x * blockDim.x + threadIdx.x;
    if (i < n) g_out_norm[i] = rsqrtf((float)max(g_deg_out[i], 1));
}

// ---- parallel exclusive scan: block-local scan + atomic block base ----
__global__ __launch_bounds__(256) void scan_kernel(int n) {
    __shared__ int s[256];
    __shared__ int base;
    const int t = threadIdx.x;
    const int i = blockIdx.x * 256 + t;
    int d = (i < n) ? g_deg_in[i] : 0;
    s[t] = d;
    __syncthreads();
#pragma unroll
    for (int off = 1; off < 256; off <<= 1) {
        int v = (t >= off) ? s[t - off] : 0;
        __syncthreads();
        s[t] += v;
        __syncthreads();
    }
    if (t == 255) base = atomicAdd(&g_base_ctr, s[255]);
    __syncthreads();
    if (i < n) {
        int o = base + s[t] - d;
        g_off[i] = o;
        g_cursor[i] = o;
    }
}

// ---- CSR fill: group edge sources by destination ----
__global__ void fill_kernel(const int* __restrict__ src,
                            const int* __restrict__ dst, int e) {
    int i = blockIdx.x * blockDim.x + threadIdx.x;
    if (i < e) {
        int p = atomicAdd(&g_cursor[dst[i]], 1);
        g_esrc[p] = src[i];
    }
}

// ============================================================
// Tensor-core GEMM v4, fp16 2-term (B = Bh + Bl; A single fp16):
//   g_x = (h * out_norm[:,None]) @ W   (output stored fp16)
// 256 threads: 8 warps as 2(m) x 4(n); warp tile 64x32.
//   -> 8 ldmatrix.x4 per 32 HMMA (128B smem/MMA, was 192B)
// KT=32, double-buffered; ~60KB smem + <=124 regs => 2 CTAs/SM.
// ============================================================
#define KT 32
#define LDP 40   // padded row length in halves (80B stride, ldmatrix-clean)
#define STG (128 * LDP)

#define SA(st)  ((st) * STG)
#define SBH(st) ((2 + (st)) * STG)
#define SBL(st) ((4 + (st)) * STG)
#define SM_HALVES (6 * STG)
#define SM_BYTES (SM_HALVES * 2)   // 61440

#define MMA_F16(D, A, B0, B1)                                                \
    asm volatile(                                                            \
        "mma.sync.aligned.m16n8k16.row.col.f32.f16.f16.f32 "                 \
        "{%0,%1,%2,%3}, {%4,%5,%6,%7}, {%8,%9}, {%0,%1,%2,%3};"              \
        : "+f"((D)[0]), "+f"((D)[1]), "+f"((D)[2]), "+f"((D)[3])             \
        : "r"((A)[0]), "r"((A)[1]), "r"((A)[2]), "r"((A)[3]),                \
          "r"(B0), "r"(B1))

#define LDMX4(R, PTR)                                                        \
    do {                                                                     \
        uint32_t _a = (uint32_t)__cvta_generic_to_shared(PTR);               \
        asm volatile(                                                        \
            "ldmatrix.sync.aligned.m8n8.x4.shared.b16 {%0,%1,%2,%3}, [%4];"  \
            : "=r"((R)[0]), "=r"((R)[1]), "=r"((R)[2]), "=r"((R)[3])         \
            : "r"(_a));                                                      \
    } while (0)

#define CPA16(DST_PTR, SRC_PTR)                                              \
    do {                                                                     \
        uint32_t _d = (uint32_t)__cvta_generic_to_shared(DST_PTR);           \
        asm volatile("cp.async.cg.shared.global [%0], [%1], 16;"             \
                     :: "r"(_d), "l"(SRC_PTR));                              \
    } while (0)

__global__ __launch_bounds__(256, 2) void gemm_mma_kernel(
    const float* __restrict__ hin, int n) {
    extern __shared__ uint16_t sm[];
    const int tid = threadIdx.x;
    const int wid = tid >> 5;
    const int lid = tid & 31;
    const int g = lid >> 2;          // groupID
    const int t = lid & 3;           // threadID_in_group
    const int wm = (wid & 1) * 64;   // warp row base (2 m-tiles of warps)
    const int wn = (wid >> 1) * 32;  // warp col base (4 n-tiles of warps)
    const int brow = blockIdx.x * 128;
    // ldmatrix lane -> (row offset, col offset) within a 16x16 tile
    const int ro = ((lid >> 3) & 1) * 8 + (lid & 7);
    const int co = (lid >> 4) * 8;

    float d[4][4][4];
#pragma unroll
    for (int mf = 0; mf < 4; mf++)
#pragma unroll
        for (int nf = 0; nf < 4; nf++)
#pragma unroll
            for (int q = 0; q < 4; q++) d[mf][nf][q] = 0.f;

    // A mapping: row = tid/2, 16 fp32 per thread per 32-chunk
    const int arow  = tid >> 1;
    const int acol  = (tid & 1) * 16;
    const int agrow = brow + arow;
    const bool a_ok = agrow < n;
    const float s   = a_ok ? g_out_norm[agrow] : 0.f;
    // B mapping: n-row = tid/2, 16-half segment per thread
    const int bn   = tid >> 1;
    const int bseg = (tid & 1) * 16;

    float4 areg[4];
    // prologue: stage A chunk 0 into registers, cp.async B chunk 0 -> stage 0
#pragma unroll
    for (int i = 0; i < 4; i++)
        areg[i] = a_ok ? *reinterpret_cast<const float4*>(
                             &hin[(size_t)agrow * F + acol + i * 4])
                       : make_float4(0.f, 0.f, 0.f, 0.f);
    CPA16(&sm[SBH(0) + bn * LDP + bseg],     &g_Wh[(size_t)bn * F + bseg]);
    CPA16(&sm[SBH(0) + bn * LDP + bseg + 8], &g_Wh[(size_t)bn * F + bseg + 8]);
    CPA16(&sm[SBL(0) + bn * LDP + bseg],     &g_Wl[(size_t)bn * F + bseg]);
    CPA16(&sm[SBL(0) + bn * LDP + bseg + 8], &g_Wl[(size_t)bn * F + bseg + 8]);
    asm volatile("cp.async.commit_group;");

    for (int c = 0; c < F / KT; c++) {
        const int st = c & 1;

        // convert staged A registers -> fp16 smem (stage st)
#pragma unroll
        for (int i = 0; i < 4; i++) {
            __half2 p01 = __float22half2_rn(
                make_float2(areg[i].x * s, areg[i].y * s));
            __half2 p23 = __float22half2_rn(
                make_float2(areg[i].z * s, areg[i].w * s));
            uint2 hp;
            hp.x = *reinterpret_cast<uint32_t*>(&p01);
            hp.y = *reinterpret_cast<uint32_t*>(&p23);
            *reinterpret_cast<uint2*>(
                &sm[SA(st) + arow * LDP + acol + i * 4]) = hp;
        }
        // stage A chunk c+1 into registers (overlaps MMA below)
        if (c < F / KT - 1) {
            const int k1 = (c + 1) * KT;
#pragma unroll
            for (int i = 0; i < 4; i++)
                areg[i] = a_ok ? *reinterpret_cast<const float4*>(
                                     &hin[(size_t)agrow * F + k1 + acol + i * 4])
                               : make_float4(0.f, 0.f, 0.f, 0.f);
        }
        asm volatile("cp.async.wait_group 0;");  // B chunk c landed
        __syncthreads();  // A stores + B visible; prior MMA reads done
        // cp.async B chunk c+1 into the other stage (overlaps MMA below)
        if (c < F / KT - 1) {
            const int k1 = (c + 1) * KT;
            CPA16(&sm[SBH(st ^ 1) + bn * LDP + bseg],
                  &g_Wh[(size_t)bn * F + k1 + bseg]);
            CPA16(&sm[SBH(st ^ 1) + bn * LDP + bseg + 8],
                  &g_Wh[(size_t)bn * F + k1 + bseg + 8]);
            CPA16(&sm[SBL(st ^ 1) + bn * LDP + bseg],
                  &g_Wl[(size_t)bn * F + k1 + bseg]);
            CPA16(&sm[SBL(st ^ 1) + bn * LDP + bseg + 8],
                  &g_Wl[(size_t)bn * F + k1 + bseg + 8]);
            asm volatile("cp.async.commit_group;");
        }

        // ---- MMA: 2 k-steps of 16; 8 ldmatrix + 32 HMMA each ----
#pragma unroll
        for (int ks = 0; ks < 2; ks++) {
            const int kb = ks * 16;
            uint32_t a[4][4];
#pragma unroll
            for (int mf = 0; mf < 4; mf++)
                LDMX4(a[mf], &sm[SA(st) + (wm + mf * 16 + ro) * LDP + kb + co]);
#pragma unroll
            for (int nt = 0; nt < 2; nt++) {
                uint32_t bh[4], bl[4];
                int rb = (wn + nt * 16 + ro) * LDP + kb + co;
                LDMX4(bh, &sm[SBH(st) + rb]);
                LDMX4(bl, &sm[SBL(st) + rb]);
#pragma unroll
                for (int sl = 0; sl < 2; sl++) {
#pragma unroll
                    for (int mf = 0; mf < 4; mf++) {
                        MMA_F16(d[mf][nt * 2 + sl], a[mf], bh[sl], bh[sl + 2]);
                        MMA_F16(d[mf][nt * 2 + sl], a[mf], bl[sl], bl[sl + 2]);
                    }
                }
            }
        }
        // no trailing sync: next iteration writes the other stage
    }

    // ---- epilogue: write fp16 result ----
#pragma unroll
    for (int mf = 0; mf < 4; mf++) {
        int row0 = brow + wm + mf * 16 + g;
        int row1 = row0 + 8;
#pragma unroll
        for (int nf = 0; nf < 4; nf++) {
            int col = wn + nf * 8 + 2 * t;
            __half2 lo = __float22half2_rn(make_float2(d[mf][nf][0], d[mf][nf][1]));
            __half2 hi = __float22half2_rn(make_float2(d[mf][nf][2], d[mf][nf][3]));
            if (row0 < n)
                *reinterpret_cast<__half2*>(&g_x[(size_t)row0 * H + col]) = lo;
            if (row1 < n)
                *reinterpret_cast<__half2*>(&g_x[(size_t)row1 * H + col]) = hi;
        }
    }
}

// ---- fused CSR gather + in_norm + bias + LayerNorm: warp per node ----
__global__ __launch_bounds__(256) void gather_ln_kernel(
    const float* __restrict__ bias, const float* __restrict__ gamma,
    const float* __restrict__ beta, float* __restrict__ y, int n) {
    int node = blockIdx.x * 8 + (threadIdx.x >> 5);
    if (node >= n) return;
    int lane = threadIdx.x & 31;

    const int beg = g_off[node];
    const int cnt = g_deg_in[node];

    float4 acc = make_float4(0.f, 0.f, 0.f, 0.f);
    for (int base = 0; base < cnt; base += 32) {
        int m = min(32, cnt - base);
        int id = (lane < m) ? g_esrc[beg + base + lane] : 0;
#pragma unroll 4
        for (int j = 0; j < m; j++) {
            int sidx = __shfl_sync(0xffffffffu, id, j);
            uint2 raw = *reinterpret_cast<const uint2*>(
                &g_x[(size_t)sidx * H + lane * 4]);
            float2 f01 = __half22float2(*reinterpret_cast<__half2*>(&raw.x));
            float2 f23 = __half22float2(*reinterpret_cast<__half2*>(&raw.y));
            acc.x += f01.x; acc.y += f01.y; acc.z += f23.x; acc.w += f23.y;
        }
    }

    const float si = rsqrtf((float)max(cnt, 1));
    float4 bb = *reinterpret_cast<const float4*>(&bias[lane * 4]);
    float4 v;
    v.x = acc.x * si + bb.x;
    v.y = acc.y * si + bb.y;
    v.z = acc.z * si + bb.z;
    v.w = acc.w * si + bb.w;

    float sum = v.x + v.y + v.z + v.w;
#pragma unroll
    for (int o = 16; o; o >>= 1) sum += __shfl_xor_sync(0xffffffffu, sum, o);
    float mu = sum * (1.f / 128.f);

    float dx = v.x - mu, dy = v.y - mu, dz = v.z - mu, dw = v.w - mu;
    float sq = dx * dx + dy * dy + dz * dz + dw * dw;
#pragma unroll
    for (int o = 16; o; o >>= 1) sq += __shfl_xor_sync(0xffffffffu, sq, o);
    float rstd = rsqrtf(sq * (1.f / 128.f) + 1e-5f);

    float4 gm = *reinterpret_cast<const float4*>(&gamma[lane * 4]);
    float4 be = *reinterpret_cast<const float4*>(&beta[lane * 4]);
    float4 o4;
    o4.x = dx * rstd * gm.x + be.x;
    o4.y = dy * rstd * gm.y + be.y;
    o4.z = dz * rstd * gm.z + be.z;
    o4.w = dw * rstd * gm.w + be.w;
    *reinterpret_cast<float4*>(&y[(size_t)node * H + lane * 4]) = o4;
}

extern "C" void kernel_launch(void* const* d_in, const int* in_sizes, int n_in,
                              void* d_out, int out_size) {
    const float* h     = (const float*)d_in[0];
    const int*   src   = (const int*)d_in[1];
    const int*   dst   = (const int*)d_in[2];
    const float* W     = (const float*)d_in[3];
    const float* b     = (const float*)d_in[4];
    const float* gamma = (const float*)d_in[5];
    const float* beta  = (const float*)d_in[6];
    float* y = (float*)d_out;

    int n = in_sizes[0] / F;   // 50000
    int e = in_sizes[1];       // 800000

    static bool attr_set = false;
    if (!attr_set) {
        cudaFuncSetAttribute(gemm_mma_kernel,
                             cudaFuncAttributeMaxDynamicSharedMemorySize,
                             SM_BYTES);
        attr_set = true;
    }

    zero_kernel<<<(H * F + 255) / 256, 256>>>(W, n);            // 1
    deg_kernel<<<(e / 4 + 255) / 256, 256>>>(src, dst, e);      // 2
    norm_kernel<<<(n + 255) / 256, 256>>>(n);                   // 3
    gemm_mma_kernel<<<(n + 127) / 128, 256, SM_BYTES>>>(h, n);  // 4 (profiled)
    scan_kernel<<<(n + 255) / 256, 256>>>(n);                   // 5
    fill_kernel<<<(e + 255) / 256, 256>>>(src, dst, e);         // 6
    gather_ln_kernel<<<(n + 7) / 8, 256>>>(b, gamma, beta, y, n); // 7
}

// round 9
// speedup vs baseline: 2.9713x; 1.1171x over previous
#include <cuda_runtime.h>
#include <cuda_fp16.h>
#include <cstdint>

#define NMAX 50000
#define EMAX 800000
#define F 512
#define H 128

// ---- scratch (static device globals: no allocation allowed) ----
__device__ __half   g_x[(size_t)NMAX * H];     // (h*out_norm) @ W, fp16
__device__ int      g_deg_out[NMAX];
__device__ int      g_deg_in[NMAX];
__device__ float    g_out_norm[NMAX];
__device__ int      g_off[NMAX];               // CSR offsets (by dst)
__device__ int      g_cursor[NMAX];            // fill cursors
__device__ int      g_esrc[EMAX];              // src ids grouped by dst
__device__ int      g_base_ctr;                // scan block-base counter
__device__ uint16_t g_Wh[(size_t)H * F];       // fp16 W^T: [n][k]

// ---- zero degrees + counter + W fp16 transpose (graph replays) ----
__global__ void zero_kernel(const float* __restrict__ W, int n) {
    int i = blockIdx.x * blockDim.x + threadIdx.x;
    if (i == 0) g_base_ctr = 0;
    if (i < n) { g_deg_out[i] = 0; g_deg_in[i] = 0; }
    if (i < H * F) {
        int nn = i >> 9;        // 0..127
        int k  = i & (F - 1);   // 0..511
        __half hv = __float2half_rn(W[(size_t)k * H + nn]);
        g_Wh[i] = *reinterpret_cast<uint16_t*>(&hv);
    }
}

// ---- degree histograms (int4 vectorized) ----
__global__ void deg_kernel(const int* __restrict__ src,
                           const int* __restrict__ dst, int e) {
    int i4 = (blockIdx.x * blockDim.x + threadIdx.x) * 4;
    if (i4 + 3 < e) {
        int4 s = *reinterpret_cast<const int4*>(&src[i4]);
        int4 d = *reinterpret_cast<const int4*>(&dst[i4]);
        atomicAdd(&g_deg_out[s.x], 1); atomicAdd(&g_deg_out[s.y], 1);
        atomicAdd(&g_deg_out[s.z], 1); atomicAdd(&g_deg_out[s.w], 1);
        atomicAdd(&g_deg_in[d.x], 1);  atomicAdd(&g_deg_in[d.y], 1);
        atomicAdd(&g_deg_in[d.z], 1);  atomicAdd(&g_deg_in[d.w], 1);
    } else {
        for (int i = i4; i < e; i++) {
            atomicAdd(&g_deg_out[src[i]], 1);
            atomicAdd(&g_deg_in[dst[i]], 1);
        }
    }
}

// ---- out-degree -> norm (in_norm computed inline in gather) ----
__global__ void norm_kernel(int n) {
    int i = blockIdx.x * blockDim.x + threadIdx.x;
    if (i < n) g_out_norm[i] = rsqrtf((float)max(g_deg_out[i], 1));
}

// ---- parallel exclusive scan: block-local scan + atomic block base ----
__global__ __launch_bounds__(256) void scan_kernel(int n) {
    __shared__ int s[256];
    __shared__ int base;
    const int t = threadIdx.x;
    const int i = blockIdx.x * 256 + t;
    int d = (i < n) ? g_deg_in[i] : 0;
    s[t] = d;
    __syncthreads();
#pragma unroll
    for (int off = 1; off < 256; off <<= 1) {
        int v = (t >= off) ? s[t - off] : 0;
        __syncthreads();
        s[t] += v;
        __syncthreads();
    }
    if (t == 255) base = atomicAdd(&g_base_ctr, s[255]);
    __syncthreads();
    if (i < n) {
        int o = base + s[t] - d;
        g_off[i] = o;
        g_cursor[i] = o;
    }
}

// ---- CSR fill: group edge sources by destination (int4 vectorized) ----
__global__ void fill_kernel(const int* __restrict__ src,
                            const int* __restrict__ dst, int e) {
    int i4 = (blockIdx.x * blockDim.x + threadIdx.x) * 4;
    if (i4 + 3 < e) {
        int4 s = *reinterpret_cast<const int4*>(&src[i4]);
        int4 d = *reinterpret_cast<const int4*>(&dst[i4]);
        g_esrc[atomicAdd(&g_cursor[d.x], 1)] = s.x;
        g_esrc[atomicAdd(&g_cursor[d.y], 1)] = s.y;
        g_esrc[atomicAdd(&g_cursor[d.z], 1)] = s.z;
        g_esrc[atomicAdd(&g_cursor[d.w], 1)] = s.w;
    } else {
        for (int i = i4; i < e; i++)
            g_esrc[atomicAdd(&g_cursor[dst[i]], 1)] = src[i];
    }
}

// ============================================================
// Tensor-core GEMM v5, single fp16 term:
//   g_x = (h * out_norm[:,None]) @ W   (output stored fp16)
// 256 threads: 8 warps as 2(m) x 4(n); warp tile 64x32.
// KT=32, double-buffered A(fp16)+B; register-staged A fp32.
// ============================================================
#define KT 32
#define LDP 40   // padded row length in halves (80B stride, ldmatrix-clean)
#define STG (128 * LDP)

#define SA(st)  ((st) * STG)
#define SBH(st) ((2 + (st)) * STG)
#define SM_HALVES (4 * STG)
#define SM_BYTES (SM_HALVES * 2)   // 40960

#define MMA_F16(D, A, B0, B1)                                                \
    asm volatile(                                                            \
        "mma.sync.aligned.m16n8k16.row.col.f32.f16.f16.f32 "                 \
        "{%0,%1,%2,%3}, {%4,%5,%6,%7}, {%8,%9}, {%0,%1,%2,%3};"              \
        : "+f"((D)[0]), "+f"((D)[1]), "+f"((D)[2]), "+f"((D)[3])             \
        : "r"((A)[0]), "r"((A)[1]), "r"((A)[2]), "r"((A)[3]),                \
          "r"(B0), "r"(B1))

#define LDMX4(R, PTR)                                                        \
    do {                                                                     \
        uint32_t _a = (uint32_t)__cvta_generic_to_shared(PTR);               \
        asm volatile(                                                        \
            "ldmatrix.sync.aligned.m8n8.x4.shared.b16 {%0,%1,%2,%3}, [%4];"  \
            : "=r"((R)[0]), "=r"((R)[1]), "=r"((R)[2]), "=r"((R)[3])         \
            : "r"(_a));                                                      \
    } while (0)

#define CPA16(DST_PTR, SRC_PTR)                                              \
    do {                                                                     \
        uint32_t _d = (uint32_t)__cvta_generic_to_shared(DST_PTR);           \
        asm volatile("cp.async.cg.shared.global [%0], [%1], 16;"             \
                     :: "r"(_d), "l"(SRC_PTR));                              \
    } while (0)

__global__ __launch_bounds__(256, 2) void gemm_mma_kernel(
    const float* __restrict__ hin, int n) {
    extern __shared__ uint16_t sm[];
    const int tid = threadIdx.x;
    const int wid = tid >> 5;
    const int lid = tid & 31;
    const int g = lid >> 2;          // groupID
    const int t = lid & 3;           // threadID_in_group
    const int wm = (wid & 1) * 64;   // warp row base (2 m-tiles of warps)
    const int wn = (wid >> 1) * 32;  // warp col base (4 n-tiles of warps)
    const int brow = blockIdx.x * 128;
    // ldmatrix lane -> (row offset, col offset) within a 16x16 tile
    const int ro = ((lid >> 3) & 1) * 8 + (lid & 7);
    const int co = (lid >> 4) * 8;

    float d[4][4][4];
#pragma unroll
    for (int mf = 0; mf < 4; mf++)
#pragma unroll
        for (int nf = 0; nf < 4; nf++)
#pragma unroll
            for (int q = 0; q < 4; q++) d[mf][nf][q] = 0.f;

    // A mapping: row = tid/2, 16 fp32 per thread per 32-chunk
    const int arow  = tid >> 1;
    const int acol  = (tid & 1) * 16;
    const int agrow = brow + arow;
    const bool a_ok = agrow < n;
    const float s   = a_ok ? g_out_norm[agrow] : 0.f;
    // B mapping: n-row = tid/2, 16-half segment per thread
    const int bn   = tid >> 1;
    const int bseg = (tid & 1) * 16;

    float4 areg[4];
    // prologue: stage A chunk 0 into registers, cp.async B chunk 0 -> stage 0
#pragma unroll
    for (int i = 0; i < 4; i++)
        areg[i] = a_ok ? *reinterpret_cast<const float4*>(
                             &hin[(size_t)agrow * F + acol + i * 4])
                       : make_float4(0.f, 0.f, 0.f, 0.f);
    CPA16(&sm[SBH(0) + bn * LDP + bseg],     &g_Wh[(size_t)bn * F + bseg]);
    CPA16(&sm[SBH(0) + bn * LDP + bseg + 8], &g_Wh[(size_t)bn * F + bseg + 8]);
    asm volatile("cp.async.commit_group;");

    for (int c = 0; c < F / KT; c++) {
        const int st = c & 1;

        // convert staged A registers -> fp16 smem (stage st)
#pragma unroll
        for (int i = 0; i < 4; i++) {
            __half2 p01 = __float22half2_rn(
                make_float2(areg[i].x * s, areg[i].y * s));
            __half2 p23 = __float22half2_rn(
                make_float2(areg[i].z * s, areg[i].w * s));
            uint2 hp;
            hp.x = *reinterpret_cast<uint32_t*>(&p01);
            hp.y = *reinterpret_cast<uint32_t*>(&p23);
            *reinterpret_cast<uint2*>(
                &sm[SA(st) + arow * LDP + acol + i * 4]) = hp;
        }
        // stage A chunk c+1 into registers (overlaps MMA below)
        if (c < F / KT - 1) {
            const int k1 = (c + 1) * KT;
#pragma unroll
            for (int i = 0; i < 4; i++)
                areg[i] = a_ok ? *reinterpret_cast<const float4*>(
                                     &hin[(size_t)agrow * F + k1 + acol + i * 4])
                               : make_float4(0.f, 0.f, 0.f, 0.f);
        }
        asm volatile("cp.async.wait_group 0;");  // B chunk c landed
        __syncthreads();  // A stores + B visible; prior MMA reads done
        // cp.async B chunk c+1 into the other stage (overlaps MMA below)
        if (c < F / KT - 1) {
            const int k1 = (c + 1) * KT;
            CPA16(&sm[SBH(st ^ 1) + bn * LDP + bseg],
                  &g_Wh[(size_t)bn * F + k1 + bseg]);
            CPA16(&sm[SBH(st ^ 1) + bn * LDP + bseg + 8],
                  &g_Wh[(size_t)bn * F + k1 + bseg + 8]);
            asm volatile("cp.async.commit_group;");
        }

        // ---- MMA: 2 k-steps of 16; 6 ldmatrix + 16 HMMA each ----
#pragma unroll
        for (int ks = 0; ks < 2; ks++) {
            const int kb = ks * 16;
            uint32_t a[4][4];
#pragma unroll
            for (int mf = 0; mf < 4; mf++)
                LDMX4(a[mf], &sm[SA(st) + (wm + mf * 16 + ro) * LDP + kb + co]);
#pragma unroll
            for (int nt = 0; nt < 2; nt++) {
                uint32_t bh[4];
                int rb = (wn + nt * 16 + ro) * LDP + kb + co;
                LDMX4(bh, &sm[SBH(st) + rb]);
#pragma unroll
                for (int sl = 0; sl < 2; sl++) {
#pragma unroll
                    for (int mf = 0; mf < 4; mf++)
                        MMA_F16(d[mf][nt * 2 + sl], a[mf], bh[sl], bh[sl + 2]);
                }
            }
        }
        // no trailing sync: next iteration writes the other stage
    }

    // ---- epilogue: write fp16 result ----
#pragma unroll
    for (int mf = 0; mf < 4; mf++) {
        int row0 = brow + wm + mf * 16 + g;
        int row1 = row0 + 8;
#pragma unroll
        for (int nf = 0; nf < 4; nf++) {
            int col = wn + nf * 8 + 2 * t;
            __half2 lo = __float22half2_rn(make_float2(d[mf][nf][0], d[mf][nf][1]));
            __half2 hi = __float22half2_rn(make_float2(d[mf][nf][2], d[mf][nf][3]));
            if (row0 < n)
                *reinterpret_cast<__half2*>(&g_x[(size_t)row0 * H + col]) = lo;
            if (row1 < n)
                *reinterpret_cast<__half2*>(&g_x[(size_t)row1 * H + col]) = hi;
        }
    }
}

// ---- fused CSR gather + in_norm + bias + LayerNorm: warp per node ----
__global__ __launch_bounds__(256) void gather_ln_kernel(
    const float* __restrict__ bias, const float* __restrict__ gamma,
    const float* __restrict__ beta, float* __restrict__ y, int n) {
    int node = blockIdx.x * 8 + (threadIdx.x >> 5);
    if (node >= n) return;
    int lane = threadIdx.x & 31;

    const int beg = g_off[node];
    const int cnt = g_deg_in[node];

    float4 acc = make_float4(0.f, 0.f, 0.f, 0.f);
    for (int base = 0; base < cnt; base += 32) {
        int m = min(32, cnt - base);
        int id = (lane < m) ? g_esrc[beg + base + lane] : 0;
#pragma unroll 4
        for (int j = 0; j < m; j++) {
            int sidx = __shfl_sync(0xffffffffu, id, j);
            uint2 raw = *reinterpret_cast<const uint2*>(
                &g_x[(size_t)sidx * H + lane * 4]);
            float2 f01 = __half22float2(*reinterpret_cast<__half2*>(&raw.x));
            float2 f23 = __half22float2(*reinterpret_cast<__half2*>(&raw.y));
            acc.x += f01.x; acc.y += f01.y; acc.z += f23.x; acc.w += f23.y;
        }
    }

    const float si = rsqrtf((float)max(cnt, 1));
    float4 bb = *reinterpret_cast<const float4*>(&bias[lane * 4]);
    float4 v;
    v.x = acc.x * si + bb.x;
    v.y = acc.y * si + bb.y;
    v.z = acc.z * si + bb.z;
    v.w = acc.w * si + bb.w;

    float sum = v.x + v.y + v.z + v.w;
#pragma unroll
    for (int o = 16; o; o >>= 1) sum += __shfl_xor_sync(0xffffffffu, sum, o);
    float mu = sum * (1.f / 128.f);

    float dx = v.x - mu, dy = v.y - mu, dz = v.z - mu, dw = v.w - mu;
    float sq = dx * dx + dy * dy + dz * dz + dw * dw;
#pragma unroll
    for (int o = 16; o; o >>= 1) sq += __shfl_xor_sync(0xffffffffu, sq, o);
    float rstd = rsqrtf(sq * (1.f / 128.f) + 1e-5f);

    float4 gm = *reinterpret_cast<const float4*>(&gamma[lane * 4]);
    float4 be = *reinterpret_cast<const float4*>(&beta[lane * 4]);
    float4 o4;
    o4.x = dx * rstd * gm.x + be.x;
    o4.y = dy * rstd * gm.y + be.y;
    o4.z = dz * rstd * gm.z + be.z;
    o4.w = dw * rstd * gm.w + be.w;
    *reinterpret_cast<float4*>(&y[(size_t)node * H + lane * 4]) = o4;
}

extern "C" void kernel_launch(void* const* d_in, const int* in_sizes, int n_in,
                              void* d_out, int out_size) {
    const float* h     = (const float*)d_in[0];
    const int*   src   = (const int*)d_in[1];
    const int*   dst   = (const int*)d_in[2];
    const float* W     = (const float*)d_in[3];
    const float* b     = (const float*)d_in[4];
    const float* gamma = (const float*)d_in[5];
    const float* beta  = (const float*)d_in[6];
    float* y = (float*)d_out;

    int n = in_sizes[0] / F;   // 50000
    int e = in_sizes[1];       // 800000

    static bool attr_set = false;
    if (!attr_set) {
        cudaFuncSetAttribute(gemm_mma_kernel,
                             cudaFuncAttributeMaxDynamicSharedMemorySize,
                             SM_BYTES);
        attr_set = true;
    }

    zero_kernel<<<(H * F + 255) / 256, 256>>>(W, n);            // 1
    deg_kernel<<<(e / 4 + 255) / 256, 256>>>(src, dst, e);      // 2
    norm_kernel<<<(n + 255) / 256, 256>>>(n);                   // 3
    gemm_mma_kernel<<<(n + 127) / 128, 256, SM_BYTES>>>(h, n);  // 4 (profiled)
    scan_kernel<<<(n + 255) / 256, 256>>>(n);                   // 5
    fill_kernel<<<(e / 4 + 255) / 256, 256>>>(src, dst, e);     // 6
    gather_ln_kernel<<<(n + 7) / 8, 256>>>(b, gamma, beta, y, n); // 7
}